// round 1
// baseline (speedup 1.0000x reference)
#include <cuda_runtime.h>
#include <math.h>

#define HW   64800
#define E_   256
#define NLAY 4
#define LM_  90
#define MM_  91
#define HID_ 512
#define H_   180
#define W_   360

// ---------------- scratch (device globals: allowed) ----------------
__device__ float  g_hA[(E_ + 2) * HW];   // h lives in rows 0..255; rows 256,257 = raw input x (for decoder concat)
__device__ float  g_hB[E_ * HW];         // scratch (enc1 out / isht out)
__device__ float  g_t [HID_ * HW];       // mlp hidden / decoder hidden
__device__ float2 g_xf [MM_ * E_ * H_];  // fwd: [m][h][c], inv: [m][c][h] (reused)
__device__ float2 g_cf [LM_ * E_ * MM_]; // [l][c][m]
__device__ float2 g_cf2[LM_ * E_ * MM_]; // [l][o][m]
__device__ float2 g_Ffwd[W_ * MM_];      // [x][m] = (cos, -sin)
__device__ float2 g_Ginv[MM_ * W_];      // [m][x] = (s*cos, -s*sin)

__device__ __forceinline__ float gelu_f(float v) {
    return 0.5f * v * (1.0f + erff(v * 0.7071067811865475f));
}

// ---------------- DFT tables ----------------
__global__ void k_init_tables() {
    int idx = blockIdx.x * blockDim.x + threadIdx.x;
    if (idx >= W_ * MM_) return;
    int x = idx / MM_, m = idx % MM_;
    int r = (m * x) % W_;                 // theta = 2*pi*m*x/360 = pi * (r/180)
    double a = (double)r / 180.0;
    double s, c;
    sincospi(a, &s, &c);
    g_Ffwd[x * MM_ + m] = make_float2((float)c, (float)(-s));
    double sc = (m == 0) ? (1.0 / 360.0) : (2.0 / 360.0);
    g_Ginv[m * W_ + x] = make_float2((float)(sc * c), (float)(-sc * s));
}

// copy raw input channels into rows 256,257 of g_hA (decoder concat)
__global__ void k_copyx(const float* __restrict__ x) {
    int i = blockIdx.x * blockDim.x + threadIdx.x;
    if (i < 2 * HW) g_hA[E_ * HW + i] = x[i];
}

// encoder stage 1: g_hB[e][p] = gelu(w[e][0]*x0[p] + w[e][1]*x1[p])
__global__ void k_enc1(const float* __restrict__ x, const float* __restrict__ w) {
    int p = blockIdx.x * blockDim.x + threadIdx.x;
    if (p >= HW) return;
    float x0 = x[p], x1 = x[HW + p];
    #pragma unroll 4
    for (int e = 0; e < E_; e++) {
        float v = w[2 * e] * x0 + w[2 * e + 1] * x1;
        g_hB[e * HW + p] = gelu_f(v);
    }
}

// ---------------- rfft over longitude: h[c][y][x] -> xf[m][y*256+c] ----------------
__global__ void k_rfft() {
    int row = blockIdx.x;              // c*180 + y
    int y = row % H_;
    __shared__ float sx[W_];
    for (int i = threadIdx.x; i < W_; i += blockDim.x) sx[i] = g_hA[row * W_ + i];
    __syncthreads();
    int m = threadIdx.x;
    if (m >= MM_) return;
    float ar = 0.f, ai = 0.f;
    #pragma unroll 4
    for (int x = 0; x < W_; x++) {
        float v = sx[x];
        float2 f = g_Ffwd[x * MM_ + m];
        ar += v * f.x;
        ai += v * f.y;
    }
    int c = row / H_;
    g_xf[m * (E_ * H_) + y * E_ + c] = make_float2(ar, ai);
}

// ---------------- Legendre forward: cf[l][c][m] = sum_h xf[m][h][c] * legf[m][l][h] ----------------
#define TL 10
__global__ void k_legfwd(const float* __restrict__ legf) {
    int m  = blockIdx.x;   // 0..90
    int lt = blockIdx.y;   // 0..8
    int c  = threadIdx.x;  // 0..255
    __shared__ float sl[TL][H_];
    for (int i = c; i < TL * H_; i += 256) {
        int j = i / H_, hh = i % H_;
        sl[j][hh] = legf[(m * LM_ + lt * TL + j) * H_ + hh];
    }
    __syncthreads();
    float2 acc[TL];
    #pragma unroll
    for (int j = 0; j < TL; j++) acc[j] = make_float2(0.f, 0.f);
    const float2* xfm = g_xf + m * (E_ * H_);
    for (int hh = 0; hh < H_; hh++) {
        float2 v = xfm[hh * E_ + c];
        #pragma unroll
        for (int j = 0; j < TL; j++) {
            float w = sl[j][hh];
            acc[j].x += v.x * w;
            acc[j].y += v.y * w;
        }
    }
    #pragma unroll
    for (int j = 0; j < TL; j++) {
        int l = lt * TL + j;
        g_cf[(l * E_ + c) * MM_ + m] = acc[j];
    }
}

// ---------------- spectral mix (per l): cf2[l][o][m] = sum_c (wr+iwi)[o][c][l] * cf[l][c][m] ----------------
#define TO 16
__global__ void k_spectral(const float* __restrict__ wr, const float* __restrict__ wi) {
    int l  = blockIdx.x;   // 0..89
    int ot = blockIdx.y;   // 0..15
    int m  = threadIdx.x;  // 0..95 (active < 91)
    __shared__ float2 sw[E_][TO];  // [c][oj] = (wr, wi)
    for (int i = threadIdx.x; i < E_ * TO; i += blockDim.x) {
        int cc = i >> 4, oj = i & 15;
        int o = ot * TO + oj;
        long base = ((long)o * E_ + cc) * LM_ + l;
        sw[cc][oj] = make_float2(wr[base], wi[base]);
    }
    __syncthreads();
    float2 acc[TO];
    #pragma unroll
    for (int j = 0; j < TO; j++) acc[j] = make_float2(0.f, 0.f);
    for (int c = 0; c < E_; c++) {
        float2 v = (m < MM_) ? g_cf[(l * E_ + c) * MM_ + m] : make_float2(0.f, 0.f);
        #pragma unroll
        for (int j = 0; j < TO; j++) {
            float2 w2 = sw[c][j];
            acc[j].x += w2.x * v.x - w2.y * v.y;
            acc[j].y += w2.x * v.y + w2.y * v.x;
        }
    }
    if (m < MM_) {
        #pragma unroll
        for (int j = 0; j < TO; j++)
            g_cf2[(l * E_ + ot * TO + j) * MM_ + m] = acc[j];
    }
}

// ---------------- Legendre inverse: xf2[m][o][h] = sum_l cf2[l][o][m] * legi[m][l][h] ----------------
__global__ void k_leginv(const float* __restrict__ legi) {
    int m  = blockIdx.x;   // 0..90
    int ot = blockIdx.y;   // 0..15
    int h  = threadIdx.x;  // 0..191 (active < 180)
    __shared__ float2 sc[LM_][TO];
    for (int i = threadIdx.x; i < LM_ * TO; i += blockDim.x) {
        int l = i / TO, oj = i % TO;
        sc[l][oj] = g_cf2[(l * E_ + ot * TO + oj) * MM_ + m];
    }
    __syncthreads();
    if (h >= H_) return;
    float2 acc[TO];
    #pragma unroll
    for (int j = 0; j < TO; j++) acc[j] = make_float2(0.f, 0.f);
    for (int l = 0; l < LM_; l++) {
        float w = legi[(m * LM_ + l) * H_ + h];
        #pragma unroll
        for (int j = 0; j < TO; j++) {
            float2 s = sc[l][j];
            acc[j].x += s.x * w;
            acc[j].y += s.y * w;
        }
    }
    #pragma unroll
    for (int j = 0; j < TO; j++)
        g_xf[m * (E_ * H_) + (ot * TO + j) * H_ + h] = acc[j];
}

// ---------------- irfft: g_hB[c][y][x] = sum_m (Xr*gc + Xi*gs) ----------------
__global__ void k_irfft() {
    int row = blockIdx.x;   // c*180 + y
    __shared__ float2 s[MM_];
    if (threadIdx.x < MM_) s[threadIdx.x] = g_xf[threadIdx.x * (E_ * H_) + row];
    __syncthreads();
    int x = threadIdx.x;
    if (x >= W_) return;
    float acc = 0.f;
    #pragma unroll 7
    for (int m = 0; m < MM_; m++) {
        float2 g = g_Ginv[m * W_ + x];
        float2 v = s[m];
        acc += v.x * g.x + v.y * g.y;
    }
    g_hB[row * W_ + x] = acc;
}

// ---------------- generic SGEMM: C[M][N] = A[M][K] * B[K][N]; EPI: 0 none, 1 gelu, 2 +ADD ----------------
#define BM 128
#define BN 128
#define BK 8
#define TM 8
#define TN 8
template <int EPI>
__global__ __launch_bounds__(256) void k_sgemm(const float* __restrict__ A,
                                               const float* __restrict__ B,
                                               float* __restrict__ C,
                                               const float* __restrict__ ADD,
                                               int M, int N, int K) {
    __shared__ float As[BK][BM];
    __shared__ float Bs[BK][BN];
    int bm = blockIdx.y * BM;
    int bn = blockIdx.x * BN;
    int tid = threadIdx.x;
    int tx = tid & 15, ty = tid >> 4;
    float acc[TM][TN];
    #pragma unroll
    for (int i = 0; i < TM; i++)
        #pragma unroll
        for (int j = 0; j < TN; j++) acc[i][j] = 0.f;

    for (int k0 = 0; k0 < K; k0 += BK) {
        #pragma unroll
        for (int i = 0; i < 4; i++) {
            int idx = tid + i * 256;
            int r = idx >> 3, cc = idx & 7;
            int gm = bm + r, gk = k0 + cc;
            As[cc][r] = (gm < M && gk < K) ? A[(long)gm * K + gk] : 0.f;
        }
        #pragma unroll
        for (int i = 0; i < 4; i++) {
            int idx = tid + i * 256;
            int r = idx >> 7, cc = idx & 127;
            int gk = k0 + r, gn = bn + cc;
            Bs[r][cc] = (gk < K && gn < N) ? B[(long)gk * N + gn] : 0.f;
        }
        __syncthreads();
        #pragma unroll
        for (int k = 0; k < BK; k++) {
            float ra[TM], rb[TN];
            #pragma unroll
            for (int i = 0; i < TM; i++) ra[i] = As[k][ty * TM + i];
            #pragma unroll
            for (int j = 0; j < TN; j++) rb[j] = Bs[k][tx * TN + j];
            #pragma unroll
            for (int i = 0; i < TM; i++)
                #pragma unroll
                for (int j = 0; j < TN; j++) acc[i][j] += ra[i] * rb[j];
        }
        __syncthreads();
    }
    #pragma unroll
    for (int i = 0; i < TM; i++) {
        int gm = bm + ty * TM + i;
        if (gm >= M) continue;
        #pragma unroll
        for (int j = 0; j < TN; j++) {
            int gn = bn + tx * TN + j;
            if (gn >= N) continue;
            float v = acc[i][j];
            if (EPI == 1) v = gelu_f(v);
            if (EPI == 2) v += ADD[(long)gm * N + gn];
            C[(long)gm * N + gn] = v;
        }
    }
}

// decoder stage 2: out[o][p] = sum_c dec_w2[o][c] * g_t[c][p], o in {0,1}
__global__ void k_dec2(const float* __restrict__ w, float* __restrict__ out) {
    int p = blockIdx.x * blockDim.x + threadIdx.x;
    if (p >= HW) return;
    float a0 = 0.f, a1 = 0.f;
    #pragma unroll 4
    for (int c = 0; c < E_; c++) {
        float v = g_t[c * HW + p];
        a0 += w[c] * v;
        a1 += w[E_ + c] * v;
    }
    out[p] = a0;
    out[HW + p] = a1;
}

extern "C" void kernel_launch(void* const* d_in, const int* in_sizes, int n_in,
                              void* d_out, int out_size) {
    const float* x        = (const float*)d_in[0];
    const float* enc_w1   = (const float*)d_in[1];
    const float* enc_w2   = (const float*)d_in[2];
    const float* pos      = (const float*)d_in[3];
    const float* leg_fwd  = (const float*)d_in[4];
    const float* leg_inv  = (const float*)d_in[5];
    const float* w_spec_r = (const float*)d_in[6];
    const float* w_spec_i = (const float*)d_in[7];
    const float* w_inner  = (const float*)d_in[8];
    const float* w_mlp1   = (const float*)d_in[9];
    const float* w_mlp2   = (const float*)d_in[10];
    const float* dec_w1   = (const float*)d_in[11];
    const float* dec_w2   = (const float*)d_in[12];
    float* out = (float*)d_out;

    float *hA, *hB, *tB;
    cudaGetSymbolAddress((void**)&hA, g_hA);
    cudaGetSymbolAddress((void**)&hB, g_hB);
    cudaGetSymbolAddress((void**)&tB, g_t);

    const int NB = (HW + BN - 1) / BN;  // 507
    dim3 gE(NB, (E_ + BM - 1) / BM);    // 507 x 2
    dim3 gH(NB, (HID_ + BM - 1) / BM);  // 507 x 4

    k_init_tables<<<(W_ * MM_ + 255) / 256, 256>>>();
    k_copyx<<<(2 * HW + 255) / 256, 256>>>(x);
    k_enc1<<<(HW + 255) / 256, 256>>>(x, enc_w1);
    // h = enc_w2 @ h1 + pos  -> g_hA
    k_sgemm<2><<<gE, 256>>>(enc_w2, hB, hA, pos, E_, HW, E_);

    for (int i = 0; i < NLAY; i++) {
        k_rfft<<<E_ * H_, 96>>>();
        k_legfwd<<<dim3(MM_, LM_ / TL), 256>>>(leg_fwd);
        k_spectral<<<dim3(LM_, E_ / TO), 96>>>(w_spec_r + (long)i * E_ * E_ * LM_,
                                               w_spec_i + (long)i * E_ * E_ * LM_);
        k_leginv<<<dim3(MM_, E_ / TO), 192>>>(leg_inv);
        k_irfft<<<E_ * H_, 384>>>();
        // g_hB (isht) += w_inner @ g_hA (residual)
        k_sgemm<2><<<gE, 256>>>(w_inner + (long)i * E_ * E_, hA, hB, hB, E_, HW, E_);
        // g_t = gelu(w_mlp1 @ g_hB)
        k_sgemm<1><<<gH, 256>>>(w_mlp1 + (long)i * HID_ * E_, hB, tB, nullptr, HID_, HW, E_);
        // g_hA = w_mlp2 @ g_t + residual(g_hA)   [in-place epilogue add]
        k_sgemm<2><<<gE, 256>>>(w_mlp2 + (long)i * E_ * HID_, tB, hA, hA, E_, HW, HID_);
    }

    // decoder: g_t = gelu(dec_w1 @ [h; x])  (g_hA has 258 rows: h + raw x)
    k_sgemm<1><<<gE, 256>>>(dec_w1, hA, tB, nullptr, E_, HW, E_ + 2);
    k_dec2<<<(HW + 255) / 256, 256>>>(dec_w2, out);
}

// round 2
// speedup vs baseline: 1.8789x; 1.8789x over previous
#include <cuda_runtime.h>
#include <cuda_fp16.h>
#include <math.h>

#define HW   64800
#define E_   256
#define NLAY 4
#define LM_  90
#define MM_  91
#define HID_ 512
#define H_   180
#define W_   360

// ---------------- scratch (device globals: allowed) ----------------
__device__ float  g_hA[E_ * HW];          // fp32 h (residual / rfft input)
__device__ float  g_hB[E_ * HW];          // fp32 isht output (inner-skip ADD source)
__device__ __half g_hA_h[(E_ + 2) * HW];  // fp16 h; rows 256,257 = raw x (decoder concat)
__device__ __half g_hB_h[E_ * HW];        // fp16 enc1-out / inner-out
__device__ __half g_t_h [HID_ * HW];      // fp16 mlp hidden / decoder hidden
__device__ float2 g_xf [MM_ * E_ * H_];   // fwd: [m][h][c], inv: [m][c][h] (reused)
__device__ float2 g_cf [LM_ * E_ * MM_];  // [l][c][m]
__device__ float2 g_cf2[LM_ * E_ * MM_];  // [l][o][m]
__device__ float2 g_Ffwd[W_ * MM_];       // [x][m] = (cos, -sin)
__device__ float2 g_Ginv[MM_ * W_];       // [m][x] = (s*cos, -s*sin)
// fp16 weights (cast per call)
__device__ __half g_w_enc2[E_ * E_];
__device__ __half g_w_inner[NLAY * E_ * E_];
__device__ __half g_w_mlp1[NLAY * HID_ * E_];
__device__ __half g_w_mlp2[NLAY * E_ * HID_];
__device__ __half g_w_dec1[E_ * 264];     // 258 padded to 264

__device__ __forceinline__ float gelu_f(float v) {
    return 0.5f * v * (1.0f + erff(v * 0.7071067811865475f));
}
__device__ __forceinline__ unsigned smem_u32(const void* p) {
    return (unsigned)__cvta_generic_to_shared(p);
}

// ---------------- DFT tables ----------------
__global__ void k_init_tables() {
    int idx = blockIdx.x * blockDim.x + threadIdx.x;
    if (idx >= W_ * MM_) return;
    int x = idx / MM_, m = idx % MM_;
    int r = (m * x) % W_;
    double a = (double)r / 180.0;
    double s, c;
    sincospi(a, &s, &c);
    g_Ffwd[x * MM_ + m] = make_float2((float)c, (float)(-s));
    double sc = (m == 0) ? (1.0 / 360.0) : (2.0 / 360.0);
    g_Ginv[m * W_ + x] = make_float2((float)(sc * c), (float)(-sc * s));
}

// ---------------- weight / input casts ----------------
__global__ void k_castw(const float* __restrict__ s, __half* __restrict__ d, int n) {
    int i = blockIdx.x * blockDim.x + threadIdx.x;
    if (i < n) d[i] = __float2half(s[i]);
}
__global__ void k_cast_dec1(const float* __restrict__ s) {
    int i = blockIdx.x * blockDim.x + threadIdx.x;
    if (i >= E_ * 264) return;
    int r = i / 264, c = i % 264;
    g_w_dec1[i] = (c < 258) ? __float2half(s[r * 258 + c]) : __half(0);
}
__global__ void k_castx(const float* __restrict__ x) {
    int i = blockIdx.x * blockDim.x + threadIdx.x;
    if (i < 2 * HW) g_hA_h[E_ * HW + i] = __float2half(x[i]);
}

// encoder stage 1: g_hB_h[e][p] = fp16(gelu(w[e][0]*x0 + w[e][1]*x1))
__global__ void k_enc1(const float* __restrict__ x, const float* __restrict__ w) {
    int p = blockIdx.x * blockDim.x + threadIdx.x;
    if (p >= HW) return;
    float x0 = x[p], x1 = x[HW + p];
    #pragma unroll 4
    for (int e = 0; e < E_; e++) {
        float v = w[2 * e] * x0 + w[2 * e + 1] * x1;
        g_hB_h[e * HW + p] = __float2half(gelu_f(v));
    }
}

// ---------------- rfft over longitude: h[c][y][x] -> xf[m][y*256+c] ----------------
__global__ void k_rfft() {
    int row = blockIdx.x;              // c*180 + y
    int y = row % H_;
    __shared__ float sx[W_];
    for (int i = threadIdx.x; i < W_; i += blockDim.x) sx[i] = g_hA[row * W_ + i];
    __syncthreads();
    int m = threadIdx.x;
    if (m >= MM_) return;
    float ar = 0.f, ai = 0.f;
    #pragma unroll 4
    for (int x = 0; x < W_; x++) {
        float v = sx[x];
        float2 f = g_Ffwd[x * MM_ + m];
        ar += v * f.x;
        ai += v * f.y;
    }
    int c = row / H_;
    g_xf[m * (E_ * H_) + y * E_ + c] = make_float2(ar, ai);
}

// ---------------- Legendre forward ----------------
#define TL 10
__global__ void k_legfwd(const float* __restrict__ legf) {
    int m  = blockIdx.x;
    int lt = blockIdx.y;
    int c  = threadIdx.x;
    __shared__ float sl[TL][H_];
    for (int i = c; i < TL * H_; i += 256) {
        int j = i / H_, hh = i % H_;
        sl[j][hh] = legf[(m * LM_ + lt * TL + j) * H_ + hh];
    }
    __syncthreads();
    float2 acc[TL];
    #pragma unroll
    for (int j = 0; j < TL; j++) acc[j] = make_float2(0.f, 0.f);
    const float2* xfm = g_xf + m * (E_ * H_);
    for (int hh = 0; hh < H_; hh++) {
        float2 v = xfm[hh * E_ + c];
        #pragma unroll
        for (int j = 0; j < TL; j++) {
            float w = sl[j][hh];
            acc[j].x += v.x * w;
            acc[j].y += v.y * w;
        }
    }
    #pragma unroll
    for (int j = 0; j < TL; j++) {
        int l = lt * TL + j;
        g_cf[(l * E_ + c) * MM_ + m] = acc[j];
    }
}

// ---------------- spectral mix ----------------
#define TO 16
__global__ void k_spectral(const float* __restrict__ wr, const float* __restrict__ wi) {
    int l  = blockIdx.x;
    int ot = blockIdx.y;
    int m  = threadIdx.x;
    __shared__ float2 sw[E_][TO];
    for (int i = threadIdx.x; i < E_ * TO; i += blockDim.x) {
        int cc = i >> 4, oj = i & 15;
        int o = ot * TO + oj;
        long base = ((long)o * E_ + cc) * LM_ + l;
        sw[cc][oj] = make_float2(wr[base], wi[base]);
    }
    __syncthreads();
    float2 acc[TO];
    #pragma unroll
    for (int j = 0; j < TO; j++) acc[j] = make_float2(0.f, 0.f);
    for (int c = 0; c < E_; c++) {
        float2 v = (m < MM_) ? g_cf[(l * E_ + c) * MM_ + m] : make_float2(0.f, 0.f);
        #pragma unroll
        for (int j = 0; j < TO; j++) {
            float2 w2 = sw[c][j];
            acc[j].x += w2.x * v.x - w2.y * v.y;
            acc[j].y += w2.x * v.y + w2.y * v.x;
        }
    }
    if (m < MM_) {
        #pragma unroll
        for (int j = 0; j < TO; j++)
            g_cf2[(l * E_ + ot * TO + j) * MM_ + m] = acc[j];
    }
}

// ---------------- Legendre inverse ----------------
__global__ void k_leginv(const float* __restrict__ legi) {
    int m  = blockIdx.x;
    int ot = blockIdx.y;
    int h  = threadIdx.x;
    __shared__ float2 sc[LM_][TO];
    for (int i = threadIdx.x; i < LM_ * TO; i += blockDim.x) {
        int l = i / TO, oj = i % TO;
        sc[l][oj] = g_cf2[(l * E_ + ot * TO + oj) * MM_ + m];
    }
    __syncthreads();
    if (h >= H_) return;
    float2 acc[TO];
    #pragma unroll
    for (int j = 0; j < TO; j++) acc[j] = make_float2(0.f, 0.f);
    for (int l = 0; l < LM_; l++) {
        float w = legi[(m * LM_ + l) * H_ + h];
        #pragma unroll
        for (int j = 0; j < TO; j++) {
            float2 s = sc[l][j];
            acc[j].x += s.x * w;
            acc[j].y += s.y * w;
        }
    }
    #pragma unroll
    for (int j = 0; j < TO; j++)
        g_xf[m * (E_ * H_) + (ot * TO + j) * H_ + h] = acc[j];
}

// ---------------- irfft ----------------
__global__ void k_irfft() {
    int row = blockIdx.x;
    __shared__ float2 s[MM_];
    if (threadIdx.x < MM_) s[threadIdx.x] = g_xf[threadIdx.x * (E_ * H_) + row];
    __syncthreads();
    int x = threadIdx.x;
    if (x >= W_) return;
    float acc = 0.f;
    #pragma unroll 7
    for (int m = 0; m < MM_; m++) {
        float2 g = g_Ginv[m * W_ + x];
        float2 v = s[m];
        acc += v.x * g.x + v.y * g.y;
    }
    g_hB[row * W_ + x] = acc;
}

// ---------------- fp16 tensor-core GEMM: C[M][N] = A[M][K] * B[K][N] ----------------
// 128x128x32 tile, 256 threads (8 warps, 2x4), mma.sync.m16n8k16 fp16->fp32.
// Epilogue flags: GELU, ADDF (C += ADD), WF32 (write fp32 C), WF16 (write fp16 Ch).
template <bool GELU, bool ADDF, bool WF32, bool WF16>
__global__ __launch_bounds__(256, 2) void k_hgemm(
    const __half* __restrict__ A, const __half* __restrict__ B,
    float* __restrict__ C, const float* __restrict__ ADD, __half* __restrict__ Ch,
    int M, int N, int K, int lda) {
    __shared__ __half As[128][40];   // [m][k] padded: conflict-free ldmatrix
    __shared__ __half Bs[32][136];   // [k][n] padded
    const int tid = threadIdx.x, lane = tid & 31, wid = tid >> 5;
    const int wm = wid >> 2, wn = wid & 3;
    const int bm = blockIdx.y * 128, bn = blockIdx.x * 128;

    float acc[4][4][4];
    #pragma unroll
    for (int i = 0; i < 4; i++)
        #pragma unroll
        for (int j = 0; j < 4; j++)
            #pragma unroll
            for (int q = 0; q < 4; q++) acc[i][j][q] = 0.f;

    for (int k0 = 0; k0 < K; k0 += 32) {
        // load A tile: 128 rows x 32 halves (A padded to lda, lda%8==0)
        {
            int r = tid >> 1, off = (tid & 1) * 16;
            const __half* p = A + (long)(bm + r) * lda + k0 + off;
            uint4 v0 = make_uint4(0, 0, 0, 0), v1 = v0;
            if (k0 + off + 8  <= lda) v0 = *(const uint4*)p;
            if (k0 + off + 16 <= lda) v1 = *(const uint4*)(p + 8);
            *(uint4*)&As[r][off]     = v0;
            *(uint4*)&As[r][off + 8] = v1;
        }
        // load B tile: 32 rows x 128 halves
        #pragma unroll
        for (int i = 0; i < 2; i++) {
            int idx = tid + i * 256;
            int kk = idx >> 4, noff = (idx & 15) * 8;
            int gk = k0 + kk, gn = bn + noff;
            uint4 v = make_uint4(0, 0, 0, 0);
            if (gk < K && gn + 8 <= N) v = *(const uint4*)(B + (long)gk * N + gn);
            *(uint4*)&Bs[kk][noff] = v;
        }
        __syncthreads();
        #pragma unroll
        for (int ks = 0; ks < 32; ks += 16) {
            unsigned a[4][4], b[4][2];
            #pragma unroll
            for (int mt = 0; mt < 4; mt++) {
                unsigned addr = smem_u32(&As[wm * 64 + mt * 16 + (lane & 15)][ks + 8 * (lane >> 4)]);
                asm volatile("ldmatrix.sync.aligned.m8n8.x4.shared.b16 {%0,%1,%2,%3},[%4];"
                             : "=r"(a[mt][0]), "=r"(a[mt][1]), "=r"(a[mt][2]), "=r"(a[mt][3])
                             : "r"(addr));
            }
            #pragma unroll
            for (int nt = 0; nt < 4; nt++) {
                unsigned addr = smem_u32(&Bs[ks + (lane & 15)][wn * 32 + nt * 8]);
                asm volatile("ldmatrix.sync.aligned.m8n8.x2.trans.shared.b16 {%0,%1},[%2];"
                             : "=r"(b[nt][0]), "=r"(b[nt][1])
                             : "r"(addr));
            }
            #pragma unroll
            for (int mt = 0; mt < 4; mt++)
                #pragma unroll
                for (int nt = 0; nt < 4; nt++)
                    asm volatile(
                        "mma.sync.aligned.m16n8k16.row.col.f32.f16.f16.f32 "
                        "{%0,%1,%2,%3},{%4,%5,%6,%7},{%8,%9},{%0,%1,%2,%3};"
                        : "+f"(acc[mt][nt][0]), "+f"(acc[mt][nt][1]),
                          "+f"(acc[mt][nt][2]), "+f"(acc[mt][nt][3])
                        : "r"(a[mt][0]), "r"(a[mt][1]), "r"(a[mt][2]), "r"(a[mt][3]),
                          "r"(b[nt][0]), "r"(b[nt][1]));
        }
        __syncthreads();
    }
    // epilogue
    const int g = lane >> 2, tq = lane & 3;
    #pragma unroll
    for (int mt = 0; mt < 4; mt++) {
        #pragma unroll
        for (int hh = 0; hh < 2; hh++) {
            int gm = bm + wm * 64 + mt * 16 + g + hh * 8;
            #pragma unroll
            for (int nt = 0; nt < 4; nt++) {
                int gn = bn + wn * 32 + nt * 8 + tq * 2;
                if (gn >= N) continue;
                float v0 = acc[mt][nt][hh * 2 + 0];
                float v1 = acc[mt][nt][hh * 2 + 1];
                if (GELU) { v0 = gelu_f(v0); v1 = gelu_f(v1); }
                if (ADDF) {
                    float2 ad = *(const float2*)&ADD[(long)gm * N + gn];
                    v0 += ad.x; v1 += ad.y;
                }
                if (WF32) *(float2*)&C[(long)gm * N + gn] = make_float2(v0, v1);
                if (WF16) *(__half2*)&Ch[(long)gm * N + gn] = __floats2half2_rn(v0, v1);
            }
        }
    }
}

// decoder stage 2: out[o][p] = sum_c dec_w2[o][c] * t_h[c][p]
__global__ void k_dec2(const float* __restrict__ w, float* __restrict__ out) {
    int p = blockIdx.x * blockDim.x + threadIdx.x;
    if (p >= HW) return;
    float a0 = 0.f, a1 = 0.f;
    #pragma unroll 4
    for (int c = 0; c < E_; c++) {
        float v = __half2float(g_t_h[c * HW + p]);
        a0 += w[c] * v;
        a1 += w[E_ + c] * v;
    }
    out[p] = a0;
    out[HW + p] = a1;
}

extern "C" void kernel_launch(void* const* d_in, const int* in_sizes, int n_in,
                              void* d_out, int out_size) {
    const float* x        = (const float*)d_in[0];
    const float* enc_w1   = (const float*)d_in[1];
    const float* enc_w2   = (const float*)d_in[2];
    const float* pos      = (const float*)d_in[3];
    const float* leg_fwd  = (const float*)d_in[4];
    const float* leg_inv  = (const float*)d_in[5];
    const float* w_spec_r = (const float*)d_in[6];
    const float* w_spec_i = (const float*)d_in[7];
    const float* w_inner  = (const float*)d_in[8];
    const float* w_mlp1   = (const float*)d_in[9];
    const float* w_mlp2   = (const float*)d_in[10];
    const float* dec_w1   = (const float*)d_in[11];
    const float* dec_w2   = (const float*)d_in[12];
    float* out = (float*)d_out;

    float *hA, *hB;
    __half *hAh, *hBh, *tH, *wEnc2, *wInn, *wM1, *wM2, *wDec1;
    cudaGetSymbolAddress((void**)&hA, g_hA);
    cudaGetSymbolAddress((void**)&hB, g_hB);
    cudaGetSymbolAddress((void**)&hAh, g_hA_h);
    cudaGetSymbolAddress((void**)&hBh, g_hB_h);
    cudaGetSymbolAddress((void**)&tH, g_t_h);
    cudaGetSymbolAddress((void**)&wEnc2, g_w_enc2);
    cudaGetSymbolAddress((void**)&wInn, g_w_inner);
    cudaGetSymbolAddress((void**)&wM1, g_w_mlp1);
    cudaGetSymbolAddress((void**)&wM2, g_w_mlp2);
    cudaGetSymbolAddress((void**)&wDec1, g_w_dec1);

    const int NB = (HW + 127) / 128;   // 507
    dim3 gE(NB, E_ / 128);             // 507 x 2
    dim3 gH(NB, HID_ / 128);           // 507 x 4

    // tables + weight casts
    k_init_tables<<<(W_ * MM_ + 255) / 256, 256>>>();
    k_castw<<<(E_ * E_ + 255) / 256, 256>>>(enc_w2, wEnc2, E_ * E_);
    k_castw<<<(NLAY * E_ * E_ + 255) / 256, 256>>>(w_inner, wInn, NLAY * E_ * E_);
    k_castw<<<(NLAY * HID_ * E_ + 255) / 256, 256>>>(w_mlp1, wM1, NLAY * HID_ * E_);
    k_castw<<<(NLAY * E_ * HID_ + 255) / 256, 256>>>(w_mlp2, wM2, NLAY * E_ * HID_);
    k_cast_dec1<<<(E_ * 264 + 255) / 256, 256>>>(dec_w1);
    k_castx<<<(2 * HW + 255) / 256, 256>>>(x);

    // encoder
    k_enc1<<<(HW + 255) / 256, 256>>>(x, enc_w1);
    // hA = enc_w2 @ hB_h + pos   (write fp32 + fp16)
    k_hgemm<false, true, true, true><<<gE, 256>>>(wEnc2, hBh, hA, pos, hAh, E_, HW, E_, E_);

    for (int i = 0; i < NLAY; i++) {
        k_rfft<<<E_ * H_, 96>>>();
        k_legfwd<<<dim3(MM_, LM_ / TL), 256>>>(leg_fwd);
        k_spectral<<<dim3(LM_, E_ / TO), 96>>>(w_spec_r + (long)i * E_ * E_ * LM_,
                                               w_spec_i + (long)i * E_ * E_ * LM_);
        k_leginv<<<dim3(MM_, E_ / TO), 192>>>(leg_inv);
        k_irfft<<<E_ * H_, 384>>>();
        // hB_h = fp16( isht(hB) + w_inner @ hA_h )   (fp16 only)
        k_hgemm<false, true, false, true><<<gE, 256>>>(wInn + (long)i * E_ * E_, hAh,
                                                       hB, hB, hBh, E_, HW, E_, E_);
        // t_h = fp16( gelu(w_mlp1 @ hB_h) )
        k_hgemm<true, false, false, true><<<gH, 256>>>(wM1 + (long)i * HID_ * E_, hBh,
                                                       hA, (const float*)nullptr, tH,
                                                       HID_, HW, E_, E_);
        // hA = w_mlp2 @ t_h + hA (residual, in-place); also refresh hA_h
        k_hgemm<false, true, true, true><<<gE, 256>>>(wM2 + (long)i * E_ * HID_, tH,
                                                      hA, hA, hAh, E_, HW, HID_, HID_);
    }

    // decoder: t_h = gelu(dec_w1 @ [h; x])  (hA_h has 258 rows, A padded to lda=264)
    k_hgemm<true, false, false, true><<<gE, 256>>>(wDec1, hAh, hA, (const float*)nullptr,
                                                   tH, E_, HW, 258, 264);
    k_dec2<<<(HW + 255) / 256, 256>>>(dec_w2, out);
}

// round 3
// speedup vs baseline: 4.4587x; 2.3731x over previous
#include <cuda_runtime.h>
#include <cuda_fp16.h>
#include <math.h>

#define HW   64800
#define E_   256
#define NLAY 4
#define LM_  90
#define MM_  91
#define HID_ 512
#define H_   180
#define W_   360

// ---------------- scratch (device globals) ----------------
__device__ float  g_hA[E_ * HW];          // fp32 h (residual)
__device__ float  g_hB[E_ * HW];          // fp32 isht output
__device__ __half g_hA_h[(E_ + 2) * HW];  // fp16 h; rows 256,257 = raw x
__device__ __half g_hB_h[E_ * HW];
__device__ __half g_t_h [HID_ * HW];
__device__ float2 g_xf [MM_ * E_ * H_];   // rfft out: [m][y][c] float2
__device__ __half g_cfh [LM_ * 512 * 96]; // legfwd out: [l][2c+ri][m], padded m->96
__device__ float  g_cf2f[LM_ * 512 * 96]; // spectral out: [l][(hi*256+o)][m]
__device__ __half g_xf2h[46080 * 184];    // leginv out: [(c,y)][2m+ri], padded ->184
__device__ __half g_F_h [W_ * 184];       // rfft DFT matrix [x][2m+ri]
__device__ __half g_Gi_h[182 * W_];       // irfft DFT matrix [2m+ri][x]
__device__ __half g_A2  [LM_ * 512 * 512];// spectral fp16 weights (per-layer, rebuilt)
// fp16 weights
__device__ __half g_w_enc2[E_ * E_];
__device__ __half g_w_inner[NLAY * E_ * E_];
__device__ __half g_w_mlp1[NLAY * HID_ * E_];
__device__ __half g_w_mlp2[NLAY * E_ * HID_];
__device__ __half g_w_dec1[E_ * 264];

__device__ __forceinline__ float gelu_f(float v) {
    return 0.5f * v * (1.0f + erff(v * 0.7071067811865475f));
}
__device__ __forceinline__ unsigned smem_u32(const void* p) {
    return (unsigned)__cvta_generic_to_shared(p);
}

// ---------------- DFT tables (fp16) ----------------
__global__ void k_init_tables() {
    int idx = blockIdx.x * blockDim.x + threadIdx.x;
    // forward table: 360 x 184
    if (idx < W_ * 184) {
        int x = idx / 184, col = idx % 184;
        float v = 0.f;
        if (col < 182) {
            int m = col >> 1, ri = col & 1;
            int r = (m * x) % W_;
            double s, c;
            sincospi((double)r / 180.0, &s, &c);
            v = ri ? (float)(-s) : (float)c;
        }
        g_F_h[idx] = __float2half(v);
    }
    // inverse table: 182 x 360
    if (idx < 182 * W_) {
        int k = idx / W_, x = idx % W_;
        int m = k >> 1, ri = k & 1;
        int r = (m * x) % W_;
        double s, c;
        sincospi((double)r / 180.0, &s, &c);
        double sc = (m == 0) ? (1.0 / 360.0) : (2.0 / 360.0);
        g_Gi_h[idx] = __float2half(ri ? (float)(-sc * s) : (float)(sc * c));
    }
}

__global__ void k_zero_cfh() {  // zero once so pad cols m=91..95 stay 0
    int i = blockIdx.x * blockDim.x + threadIdx.x;
    if (i < LM_ * 512 * 96 / 8) ((uint4*)g_cfh)[i] = make_uint4(0, 0, 0, 0);
}

// build spectral fp16 weight block for one layer:
// A2[l][o2][k]: o2<256 -> real-out row: k=2c -> wr, k=2c+1 -> -wi
//              o2>=256 -> imag-out row: k=2c -> wi, k=2c+1 ->  wr
__global__ void k_buildA2(const float* __restrict__ wr, const float* __restrict__ wi) {
    long idx = (long)blockIdx.x * blockDim.x + threadIdx.x;
    if (idx >= (long)LM_ * 512 * 512) return;
    int k  = idx & 511;
    int o2 = (idx >> 9) & 511;
    int l  = idx >> 18;
    int c = k >> 1, ri = k & 1, oo = o2 & 255, hi = o2 >> 8;
    long wb = ((long)oo * E_ + c) * LM_ + l;
    float v = hi ? (ri ? wr[wb] : wi[wb]) : (ri ? -wi[wb] : wr[wb]);
    g_A2[idx] = __float2half(v);
}

// ---------------- weight / input casts ----------------
__global__ void k_castw(const float* __restrict__ s, __half* __restrict__ d, int n) {
    int i = blockIdx.x * blockDim.x + threadIdx.x;
    if (i < n) d[i] = __float2half(s[i]);
}
__global__ void k_cast_dec1(const float* __restrict__ s) {
    int i = blockIdx.x * blockDim.x + threadIdx.x;
    if (i >= E_ * 264) return;
    int r = i / 264, c = i % 264;
    g_w_dec1[i] = (c < 258) ? __float2half(s[r * 258 + c]) : __half(0);
}
__global__ void k_castx(const float* __restrict__ x) {
    int i = blockIdx.x * blockDim.x + threadIdx.x;
    if (i < 2 * HW) g_hA_h[E_ * HW + i] = __float2half(x[i]);
}

// encoder stage 1
__global__ void k_enc1(const float* __restrict__ x, const float* __restrict__ w) {
    int p = blockIdx.x * blockDim.x + threadIdx.x;
    if (p >= HW) return;
    float x0 = x[p], x1 = x[HW + p];
    #pragma unroll 4
    for (int e = 0; e < E_; e++) {
        float v = w[2 * e] * x0 + w[2 * e + 1] * x1;
        g_hB_h[e * HW + p] = __float2half(gelu_f(v));
    }
}

// ---------------- Legendre forward (fp32 in, fp16 interleaved out) ----------------
#define TL 10
__global__ void k_legfwd(const float* __restrict__ legf) {
    int m  = blockIdx.x;   // 0..90
    int lt = blockIdx.y;   // 0..8
    int c  = threadIdx.x;  // 0..255
    __shared__ float sl[TL][H_];
    for (int i = c; i < TL * H_; i += 256) {
        int j = i / H_, hh = i % H_;
        sl[j][hh] = legf[(m * LM_ + lt * TL + j) * H_ + hh];
    }
    __syncthreads();
    float2 acc[TL];
    #pragma unroll
    for (int j = 0; j < TL; j++) acc[j] = make_float2(0.f, 0.f);
    const float2* xfm = g_xf + m * (E_ * H_);
    for (int hh = 0; hh < H_; hh++) {
        float2 v = xfm[hh * E_ + c];
        #pragma unroll
        for (int j = 0; j < TL; j++) {
            float w = sl[j][hh];
            acc[j].x += v.x * w;
            acc[j].y += v.y * w;
        }
    }
    #pragma unroll
    for (int j = 0; j < TL; j++) {
        int l = lt * TL + j;
        long base = ((long)l * 512 + 2 * c) * 96 + m;
        g_cfh[base]      = __float2half(acc[j].x);
        g_cfh[base + 96] = __float2half(acc[j].y);
    }
}

// ---------------- Legendre inverse (fp32 in, fp16 out for irfft GEMM) ----------------
#define TO 16
__global__ void k_leginv(const float* __restrict__ legi) {
    int m  = blockIdx.x;   // 0..90
    int ot = blockIdx.y;   // 0..15
    int h  = threadIdx.x;  // 0..191
    __shared__ float scr[LM_][TO], sci[LM_][TO];
    for (int i = threadIdx.x; i < LM_ * TO; i += 192) {
        int l = i / TO, oj = i % TO;
        int o = ot * TO + oj;
        scr[l][oj] = g_cf2f[((long)l * 512 + o) * 96 + m];
        sci[l][oj] = g_cf2f[((long)l * 512 + 256 + o) * 96 + m];
    }
    __syncthreads();
    if (h >= H_) return;
    float2 acc[TO];
    #pragma unroll
    for (int j = 0; j < TO; j++) acc[j] = make_float2(0.f, 0.f);
    for (int l = 0; l < LM_; l++) {
        float w = legi[(m * LM_ + l) * H_ + h];
        #pragma unroll
        for (int j = 0; j < TO; j++) {
            acc[j].x += scr[l][j] * w;
            acc[j].y += sci[l][j] * w;
        }
    }
    #pragma unroll
    for (int j = 0; j < TO; j++) {
        int o = ot * TO + j;
        long addr = ((long)o * H_ + h) * 184 + 2 * m;
        *(__half2*)&g_xf2h[addr] = __floats2half2_rn(acc[j].x, acc[j].y);
    }
}

// ---------------- fp16 tensor-core GEMM ----------------
// MODE 0: standard epilogue (GELU/ADDF/WF32/WF16). MODE 1: rfft scatter to g_xf.
template <int MODE, bool GELU, bool ADDF, bool WF32, bool WF16>
__global__ __launch_bounds__(256, 2) void k_hgemm(
    const __half* __restrict__ A, const __half* __restrict__ B,
    float* __restrict__ C, const float* __restrict__ ADD, __half* __restrict__ Ch,
    int M, int N, int K, int lda, long sA, long sB, long sC) {
    __shared__ __half As[128][40];
    __shared__ __half Bs[32][136];
    const int tid = threadIdx.x, lane = tid & 31, wid = tid >> 5;
    const int wm = wid >> 2, wn = wid & 3;
    const int bm = blockIdx.y * 128, bn = blockIdx.x * 128;
    A += (long)blockIdx.z * sA;
    B += (long)blockIdx.z * sB;
    if (WF32) C += (long)blockIdx.z * sC;

    float acc[4][4][4];
    #pragma unroll
    for (int i = 0; i < 4; i++)
        #pragma unroll
        for (int j = 0; j < 4; j++)
            #pragma unroll
            for (int q = 0; q < 4; q++) acc[i][j][q] = 0.f;

    for (int k0 = 0; k0 < K; k0 += 32) {
        {
            int r = tid >> 1, off = (tid & 1) * 16;
            const __half* p = A + (long)(bm + r) * lda + k0 + off;
            uint4 v0 = make_uint4(0, 0, 0, 0), v1 = v0;
            if (k0 + off + 8  <= lda) v0 = *(const uint4*)p;
            if (k0 + off + 16 <= lda) v1 = *(const uint4*)(p + 8);
            *(uint4*)&As[r][off]     = v0;
            *(uint4*)&As[r][off + 8] = v1;
        }
        #pragma unroll
        for (int i = 0; i < 2; i++) {
            int idx = tid + i * 256;
            int kk = idx >> 4, noff = (idx & 15) * 8;
            int gk = k0 + kk, gn = bn + noff;
            uint4 v = make_uint4(0, 0, 0, 0);
            if (gk < K && gn + 8 <= N) v = *(const uint4*)(B + (long)gk * N + gn);
            *(uint4*)&Bs[kk][noff] = v;
        }
        __syncthreads();
        #pragma unroll
        for (int ks = 0; ks < 32; ks += 16) {
            unsigned a[4][4], b[4][2];
            #pragma unroll
            for (int mt = 0; mt < 4; mt++) {
                unsigned addr = smem_u32(&As[wm * 64 + mt * 16 + (lane & 15)][ks + 8 * (lane >> 4)]);
                asm volatile("ldmatrix.sync.aligned.m8n8.x4.shared.b16 {%0,%1,%2,%3},[%4];"
                             : "=r"(a[mt][0]), "=r"(a[mt][1]), "=r"(a[mt][2]), "=r"(a[mt][3])
                             : "r"(addr));
            }
            #pragma unroll
            for (int nt = 0; nt < 4; nt++) {
                unsigned addr = smem_u32(&Bs[ks + (lane & 15)][wn * 32 + nt * 8]);
                asm volatile("ldmatrix.sync.aligned.m8n8.x2.trans.shared.b16 {%0,%1},[%2];"
                             : "=r"(b[nt][0]), "=r"(b[nt][1])
                             : "r"(addr));
            }
            #pragma unroll
            for (int mt = 0; mt < 4; mt++)
                #pragma unroll
                for (int nt = 0; nt < 4; nt++)
                    asm volatile(
                        "mma.sync.aligned.m16n8k16.row.col.f32.f16.f16.f32 "
                        "{%0,%1,%2,%3},{%4,%5,%6,%7},{%8,%9},{%0,%1,%2,%3};"
                        : "+f"(acc[mt][nt][0]), "+f"(acc[mt][nt][1]),
                          "+f"(acc[mt][nt][2]), "+f"(acc[mt][nt][3])
                        : "r"(a[mt][0]), "r"(a[mt][1]), "r"(a[mt][2]), "r"(a[mt][3]),
                          "r"(b[nt][0]), "r"(b[nt][1]));
        }
        __syncthreads();
    }
    const int g = lane >> 2, tq = lane & 3;
    #pragma unroll
    for (int mt = 0; mt < 4; mt++) {
        #pragma unroll
        for (int hh = 0; hh < 2; hh++) {
            int gm = bm + wm * 64 + mt * 16 + g + hh * 8;
            if (MODE == 1) {
                int c = gm / H_, y = gm - c * H_;
                #pragma unroll
                for (int nt = 0; nt < 4; nt++) {
                    int gn = bn + wn * 32 + nt * 8 + tq * 2;
                    if (gn >= 2 * MM_) continue;
                    int m = gn >> 1;
                    g_xf[(long)m * (E_ * H_) + y * E_ + c] =
                        make_float2(acc[mt][nt][hh * 2], acc[mt][nt][hh * 2 + 1]);
                }
            } else {
                if (gm >= M) continue;
                #pragma unroll
                for (int nt = 0; nt < 4; nt++) {
                    int gn = bn + wn * 32 + nt * 8 + tq * 2;
                    if (gn >= N) continue;
                    float v0 = acc[mt][nt][hh * 2 + 0];
                    float v1 = acc[mt][nt][hh * 2 + 1];
                    if (GELU) { v0 = gelu_f(v0); v1 = gelu_f(v1); }
                    if (ADDF) {
                        float2 ad = *(const float2*)&ADD[(long)gm * N + gn];
                        v0 += ad.x; v1 += ad.y;
                    }
                    if (WF32) *(float2*)&C[(long)gm * N + gn] = make_float2(v0, v1);
                    if (WF16) *(__half2*)&Ch[(long)gm * N + gn] = __floats2half2_rn(v0, v1);
                }
            }
        }
    }
}

// decoder stage 2
__global__ void k_dec2(const float* __restrict__ w, float* __restrict__ out) {
    int p = blockIdx.x * blockDim.x + threadIdx.x;
    if (p >= HW) return;
    float a0 = 0.f, a1 = 0.f;
    #pragma unroll 4
    for (int c = 0; c < E_; c++) {
        float v = __half2float(g_t_h[c * HW + p]);
        a0 += w[c] * v;
        a1 += w[E_ + c] * v;
    }
    out[p] = a0;
    out[HW + p] = a1;
}

extern "C" void kernel_launch(void* const* d_in, const int* in_sizes, int n_in,
                              void* d_out, int out_size) {
    const float* x        = (const float*)d_in[0];
    const float* enc_w1   = (const float*)d_in[1];
    const float* enc_w2   = (const float*)d_in[2];
    const float* pos      = (const float*)d_in[3];
    const float* leg_fwd  = (const float*)d_in[4];
    const float* leg_inv  = (const float*)d_in[5];
    const float* w_spec_r = (const float*)d_in[6];
    const float* w_spec_i = (const float*)d_in[7];
    const float* w_inner  = (const float*)d_in[8];
    const float* w_mlp1   = (const float*)d_in[9];
    const float* w_mlp2   = (const float*)d_in[10];
    const float* dec_w1   = (const float*)d_in[11];
    const float* dec_w2   = (const float*)d_in[12];
    float* out = (float*)d_out;

    float *hA, *hB, *cf2f;
    __half *hAh, *hBh, *tH, *wEnc2, *wInn, *wM1, *wM2, *wDec1, *Fh, *Gih, *xf2h, *A2;
    cudaGetSymbolAddress((void**)&hA, g_hA);
    cudaGetSymbolAddress((void**)&hB, g_hB);
    cudaGetSymbolAddress((void**)&cf2f, g_cf2f);
    cudaGetSymbolAddress((void**)&hAh, g_hA_h);
    cudaGetSymbolAddress((void**)&hBh, g_hB_h);
    cudaGetSymbolAddress((void**)&tH, g_t_h);
    cudaGetSymbolAddress((void**)&wEnc2, g_w_enc2);
    cudaGetSymbolAddress((void**)&wInn, g_w_inner);
    cudaGetSymbolAddress((void**)&wM1, g_w_mlp1);
    cudaGetSymbolAddress((void**)&wM2, g_w_mlp2);
    cudaGetSymbolAddress((void**)&wDec1, g_w_dec1);
    cudaGetSymbolAddress((void**)&Fh, g_F_h);
    cudaGetSymbolAddress((void**)&Gih, g_Gi_h);
    cudaGetSymbolAddress((void**)&xf2h, g_xf2h);
    cudaGetSymbolAddress((void**)&A2, g_A2);
    __half* cfh;
    cudaGetSymbolAddress((void**)&cfh, g_cfh);

    const int NB = (HW + 127) / 128;   // 507
    dim3 gE(NB, E_ / 128);             // 507 x 2
    dim3 gH(NB, HID_ / 128);           // 507 x 4
    dim3 gRF(2, 360);                  // rfft:  M=46080, N(pad)=184
    dim3 gIR(3, 360);                  // irfft: M=46080, N=360
    dim3 gSP(1, 4, LM_);               // spectral: M=512, N=96, batch l

    k_init_tables<<<(W_ * 184 + 255) / 256, 256>>>();
    k_zero_cfh<<<(LM_ * 512 * 96 / 8 + 255) / 256, 256>>>();
    k_castw<<<(E_ * E_ + 255) / 256, 256>>>(enc_w2, wEnc2, E_ * E_);
    k_castw<<<(NLAY * E_ * E_ + 255) / 256, 256>>>(w_inner, wInn, NLAY * E_ * E_);
    k_castw<<<(NLAY * HID_ * E_ + 255) / 256, 256>>>(w_mlp1, wM1, NLAY * HID_ * E_);
    k_castw<<<(NLAY * E_ * HID_ + 255) / 256, 256>>>(w_mlp2, wM2, NLAY * E_ * HID_);
    k_cast_dec1<<<(E_ * 264 + 255) / 256, 256>>>(dec_w1);
    k_castx<<<(2 * HW + 255) / 256, 256>>>(x);

    k_enc1<<<(HW + 255) / 256, 256>>>(x, enc_w1);
    k_hgemm<0, false, true, true, true><<<gE, 256>>>(wEnc2, hBh, hA, pos, hAh,
                                                     E_, HW, E_, E_, 0, 0, 0);

    for (int i = 0; i < NLAY; i++) {
        // rfft: g_xf[m][y][c] = DFT(hA_h rows)
        k_hgemm<1, false, false, false, false><<<gRF, 256>>>(
            hAh, Fh, nullptr, nullptr, nullptr, 46080, 184, W_, W_, 0, 0, 0);
        k_legfwd<<<dim3(MM_, LM_ / TL), 256>>>(leg_fwd);
        // per-layer spectral weights
        k_buildA2<<<(int)(((long)LM_ * 512 * 512 + 255) / 256), 256>>>(
            w_spec_r + (long)i * E_ * E_ * LM_, w_spec_i + (long)i * E_ * E_ * LM_);
        // spectral: cf2f[l] = A2[l] @ cfh[l]
        k_hgemm<0, false, false, true, false><<<gSP, 256>>>(
            A2, cfh, cf2f, nullptr, nullptr, 512, 96, 512, 512,
            (long)512 * 512, (long)512 * 96, (long)512 * 96);
        k_leginv<<<dim3(MM_, E_ / TO), 192>>>(leg_inv);
        // irfft: hB = xf2h @ Ginv
        k_hgemm<0, false, false, true, false><<<gIR, 256>>>(
            xf2h, Gih, hB, nullptr, nullptr, 46080, W_, 182, 184, 0, 0, 0);
        // hB_h = fp16( hB + w_inner @ hA_h )
        k_hgemm<0, false, true, false, true><<<gE, 256>>>(wInn + (long)i * E_ * E_, hAh,
                                                          hB, hB, hBh, E_, HW, E_, E_, 0, 0, 0);
        // t_h = fp16( gelu(w_mlp1 @ hB_h) )
        k_hgemm<0, true, false, false, true><<<gH, 256>>>(wM1 + (long)i * HID_ * E_, hBh,
                                                          hA, nullptr, tH, HID_, HW, E_, E_, 0, 0, 0);
        // hA = w_mlp2 @ t_h + hA ; refresh hA_h
        k_hgemm<0, false, true, true, true><<<gE, 256>>>(wM2 + (long)i * E_ * HID_, tH,
                                                         hA, hA, hAh, E_, HW, HID_, HID_, 0, 0, 0);
    }

    k_hgemm<0, true, false, false, true><<<gE, 256>>>(wDec1, hAh, hA, nullptr,
                                                      tH, E_, HW, 258, 264, 0, 0, 0);
    k_dec2<<<(HW + 255) / 256, 256>>>(dec_w2, out);
}

// round 4
// speedup vs baseline: 5.1384x; 1.1524x over previous
#include <cuda_runtime.h>
#include <cuda_fp16.h>
#include <math.h>

#define HW   64800
#define E_   256
#define NLAY 4
#define LM_  90
#define MM_  91
#define HID_ 512
#define H_   180
#define W_   360

// ---------------- scratch (device globals) ----------------
__device__ float  g_hA[E_ * HW];           // fp32 h (residual)
__device__ float  g_hB[E_ * HW];           // fp32 isht output
__device__ __half g_hA_h[(E_ + 2) * HW];   // fp16 h; rows 256,257 = raw x
__device__ __half g_hB_h[E_ * HW];
__device__ __half g_t_h [HID_ * HW];
__device__ __half g_xfh [MM_ * H_ * 512];  // rfft out: [m][y][2c+ri]
__device__ __half g_cfh [LM_ * 512 * 96];  // legfwd out: [l][2c+ri][m] (m pad 96)
__device__ __half g_cf2h[MM_ * 512 * 96];  // spectral out: [m][o2][l] (l pad 96)
__device__ __half g_xf2h[46080 * 184];     // leginv out: [(o,y)][2m+ri] (pad 184)
__device__ __half g_F_h [W_ * 184];        // rfft DFT [x][2m+ri]
__device__ __half g_Gi_h[182 * W_];        // irfft DFT [2m+ri][x]
__device__ __half g_legf_h[MM_ * LM_ * 184 + 64 * 184]; // [m][l][h pad 184] + overrun pad
__device__ __half g_legi_h[MM_ * LM_ * 184];            // [m][l][h pad 184]
__device__ __half g_A2  [LM_ * 512 * 512]; // spectral fp16 weights (rebuilt per layer)
// fp16 weights
__device__ __half g_w_enc2[E_ * E_];
__device__ __half g_w_inner[NLAY * E_ * E_];
__device__ __half g_w_mlp1[NLAY * HID_ * E_];
__device__ __half g_w_mlp2[NLAY * E_ * HID_];
__device__ __half g_w_dec1[E_ * 264];

__device__ __forceinline__ float gelu_f(float v) {
    return 0.5f * v * (1.0f + erff(v * 0.7071067811865475f));
}
__device__ __forceinline__ unsigned smem_u32(const void* p) {
    return (unsigned)__cvta_generic_to_shared(p);
}
__device__ __forceinline__ void cp16(void* s, const void* g, bool p) {
    unsigned sa = smem_u32(s);
    asm volatile("cp.async.cg.shared.global [%0],[%1],16,%2;\n"
                 :: "r"(sa), "l"(g), "r"(p ? 16 : 0));
}

// ---------------- DFT tables ----------------
__global__ void k_init_tables() {
    int idx = blockIdx.x * blockDim.x + threadIdx.x;
    if (idx < W_ * 184) {
        int x = idx / 184, col = idx % 184;
        float v = 0.f;
        if (col < 182) {
            int m = col >> 1, ri = col & 1;
            int r = (m * x) % W_;
            double s, c;
            sincospi((double)r / 180.0, &s, &c);
            v = ri ? (float)(-s) : (float)c;
        }
        g_F_h[idx] = __float2half(v);
    }
    if (idx < 182 * W_) {
        int k = idx / W_, x = idx % W_;
        int m = k >> 1, ri = k & 1;
        int r = (m * x) % W_;
        double s, c;
        sincospi((double)r / 180.0, &s, &c);
        double sc = (m == 0) ? (1.0 / 360.0) : (2.0 / 360.0);
        g_Gi_h[idx] = __float2half(ri ? (float)(-sc * s) : (float)(sc * c));
    }
}

__global__ void k_zero_cfh() {  // pad cols m=91..95 must stay 0
    int i = blockIdx.x * blockDim.x + threadIdx.x;
    if (i < LM_ * 512 * 96 / 8) ((uint4*)g_cfh)[i] = make_uint4(0, 0, 0, 0);
}

// leg cast: [m][l][h<180] -> fp16 [m][l][184], pad 0
__global__ void k_cast_leg(const float* __restrict__ s, __half* __restrict__ d) {
    int i = blockIdx.x * blockDim.x + threadIdx.x;
    if (i >= MM_ * LM_ * 184) return;
    int col = i % 184, row = i / 184;
    d[i] = (col < H_) ? __float2half(s[row * H_ + col]) : __half(0);
}

// spectral fp16 weights for one layer (vectorized: one thread = (2c,2c+1))
__global__ void k_buildA2(const float* __restrict__ wr, const float* __restrict__ wi) {
    long idx = (long)blockIdx.x * blockDim.x + threadIdx.x;   // LM*512*256
    if (idx >= (long)LM_ * 512 * 256) return;
    int c  = idx & 255;
    int o2 = (idx >> 8) & 511;
    int l  = idx >> 17;
    int oo = o2 & 255, hi = o2 >> 8;
    long wb = ((long)oo * E_ + c) * LM_ + l;
    float r = wr[wb], im = wi[wb];
    float v0 = hi ? im : r;        // k=2c
    float v1 = hi ? r  : -im;      // k=2c+1
    *(__half2*)&g_A2[((long)l * 512 + o2) * 512 + 2 * c] = __floats2half2_rn(v0, v1);
}

// ---------------- weight / input casts ----------------
__global__ void k_castw(const float* __restrict__ s, __half* __restrict__ d, int n) {
    int i = blockIdx.x * blockDim.x + threadIdx.x;
    if (i < n) d[i] = __float2half(s[i]);
}
__global__ void k_cast_dec1(const float* __restrict__ s) {
    int i = blockIdx.x * blockDim.x + threadIdx.x;
    if (i >= E_ * 264) return;
    int r = i / 264, c = i % 264;
    g_w_dec1[i] = (c < 258) ? __float2half(s[r * 258 + c]) : __half(0);
}
__global__ void k_castx(const float* __restrict__ x) {
    int i = blockIdx.x * blockDim.x + threadIdx.x;
    if (i < 2 * HW) g_hA_h[E_ * HW + i] = __float2half(x[i]);
}

__global__ void k_enc1(const float* __restrict__ x, const float* __restrict__ w) {
    int p = blockIdx.x * blockDim.x + threadIdx.x;
    if (p >= HW) return;
    float x0 = x[p], x1 = x[HW + p];
    #pragma unroll 4
    for (int e = 0; e < E_; e++) {
        float v = w[2 * e] * x0 + w[2 * e + 1] * x1;
        g_hB_h[e * HW + p] = __float2half(gelu_f(v));
    }
}

// ---------------- fp16 tensor-core GEMM, cp.async double-buffered ----------------
// MODE 0: std epilogue. 1: rfft scatter -> g_xfh. 2: legfwd -> g_cfh.
// 3: spectral -> g_cf2h. 4: leginv -> g_xf2h.
template <int MODE, bool GELU, bool ADDF, bool WF32, bool WF16>
__global__ __launch_bounds__(256, 2) void k_hgemm(
    const __half* __restrict__ A, const __half* __restrict__ B,
    float* __restrict__ C, const float* __restrict__ ADD, __half* __restrict__ Ch,
    int M, int N, int K, int lda, long sA, long sB, long sC) {
    __shared__ __half As[2][128][40];
    __shared__ __half Bs[2][32][136];
    const int tid = threadIdx.x, lane = tid & 31, wid = tid >> 5;
    const int wm = wid >> 2, wn = wid & 3;
    const int bm = blockIdx.y * 128, bn = blockIdx.x * 128;
    const int z = blockIdx.z;
    A += (long)z * sA;
    B += (long)z * sB;
    if (WF32 && MODE == 0) C += (long)z * sC;

    // stage loader
    const int r_a = tid >> 1, off_a = (tid & 1) * 16;
    #define LOAD_STAGE(k0, buf)                                                     \
        {                                                                           \
            const __half* pA = A + (long)(bm + r_a) * lda + (k0) + off_a;           \
            bool pa0 = ((k0) + off_a + 8  <= lda);                                  \
            bool pa1 = ((k0) + off_a + 16 <= lda);                                  \
            cp16(&As[buf][r_a][off_a],     pa0 ? pA     : A, pa0);                  \
            cp16(&As[buf][r_a][off_a + 8], pa1 ? pA + 8 : A, pa1);                  \
            _Pragma("unroll")                                                       \
            for (int i = 0; i < 2; i++) {                                           \
                int idx = tid + i * 256;                                            \
                int kk = idx >> 4, noff = (idx & 15) * 8;                           \
                int gk = (k0) + kk, gn = bn + noff;                                 \
                bool pb = (gk < K && gn + 8 <= N);                                  \
                cp16(&Bs[buf][kk][noff], pb ? B + (long)gk * N + gn : B, pb);       \
            }                                                                       \
            asm volatile("cp.async.commit_group;\n" ::);                            \
        }

    float acc[4][4][4];
    #pragma unroll
    for (int i = 0; i < 4; i++)
        #pragma unroll
        for (int j = 0; j < 4; j++)
            #pragma unroll
            for (int q = 0; q < 4; q++) acc[i][j][q] = 0.f;

    LOAD_STAGE(0, 0)
    LOAD_STAGE(32, 1)

    const int nslab = (K + 31) / 32;
    for (int it = 0; it < nslab; it++) {
        asm volatile("cp.async.wait_group 1;\n" ::);
        __syncthreads();
        const int buf = it & 1;
        #pragma unroll
        for (int ks = 0; ks < 32; ks += 16) {
            unsigned a[4][4], b[4][2];
            #pragma unroll
            for (int mt = 0; mt < 4; mt++) {
                unsigned addr = smem_u32(&As[buf][wm * 64 + mt * 16 + (lane & 15)][ks + 8 * (lane >> 4)]);
                asm volatile("ldmatrix.sync.aligned.m8n8.x4.shared.b16 {%0,%1,%2,%3},[%4];"
                             : "=r"(a[mt][0]), "=r"(a[mt][1]), "=r"(a[mt][2]), "=r"(a[mt][3])
                             : "r"(addr));
            }
            #pragma unroll
            for (int nt = 0; nt < 4; nt++) {
                unsigned addr = smem_u32(&Bs[buf][ks + (lane & 15)][wn * 32 + nt * 8]);
                asm volatile("ldmatrix.sync.aligned.m8n8.x2.trans.shared.b16 {%0,%1},[%2];"
                             : "=r"(b[nt][0]), "=r"(b[nt][1])
                             : "r"(addr));
            }
            #pragma unroll
            for (int mt = 0; mt < 4; mt++)
                #pragma unroll
                for (int nt = 0; nt < 4; nt++)
                    asm volatile(
                        "mma.sync.aligned.m16n8k16.row.col.f32.f16.f16.f32 "
                        "{%0,%1,%2,%3},{%4,%5,%6,%7},{%8,%9},{%0,%1,%2,%3};"
                        : "+f"(acc[mt][nt][0]), "+f"(acc[mt][nt][1]),
                          "+f"(acc[mt][nt][2]), "+f"(acc[mt][nt][3])
                        : "r"(a[mt][0]), "r"(a[mt][1]), "r"(a[mt][2]), "r"(a[mt][3]),
                          "r"(b[nt][0]), "r"(b[nt][1]));
        }
        __syncthreads();
        int k0n = (it + 2) * 32;
        if (k0n < K) {
            LOAD_STAGE(k0n, buf)
        } else {
            asm volatile("cp.async.commit_group;\n" ::);
        }
    }
    #undef LOAD_STAGE

    // ---------------- epilogue ----------------
    const int g = lane >> 2, tq = lane & 3;
    #pragma unroll
    for (int mt = 0; mt < 4; mt++) {
        #pragma unroll
        for (int hh = 0; hh < 2; hh++) {
            int gm = bm + wm * 64 + mt * 16 + g + hh * 8;
            float vv0, vv1;
            #pragma unroll
            for (int nt = 0; nt < 4; nt++) {
                int gn = bn + wn * 32 + nt * 8 + tq * 2;
                vv0 = acc[mt][nt][hh * 2 + 0];
                vv1 = acc[mt][nt][hh * 2 + 1];
                if (MODE == 1) {                       // rfft: gn = 2m(+1)
                    if (gn < 2 * MM_) {
                        int m = gn >> 1;
                        int c = gm / H_, y = gm - c * H_;
                        *(__half2*)&g_xfh[(long)m * (H_ * 512) + y * 512 + 2 * c] =
                            __floats2half2_rn(vv0, vv1);
                    }
                } else if (MODE == 2) {                // legfwd: gm=l, gn=c2, z=m
                    if (gm < LM_) {
                        long base = ((long)gm * 512 + gn) * 96 + z;
                        g_cfh[base]      = __float2half(vv0);
                        g_cfh[base + 96] = __float2half(vv1);
                    }
                } else if (MODE == 3) {                // spectral: gm=o2, gn=m, z=l
                    if (gn < MM_)
                        g_cf2h[((long)gn * 512 + gm) * 96 + z] = __float2half(vv0);
                    if (gn + 1 < MM_)
                        g_cf2h[((long)(gn + 1) * 512 + gm) * 96 + z] = __float2half(vv1);
                } else if (MODE == 4) {                // leginv: gm=o2, gn=h, z=m
                    int oo = gm & 255, ri = gm >> 8;
                    if (gn < H_) {
                        long addr = ((long)oo * H_ + gn) * 184 + 2 * z + ri;
                        g_xf2h[addr] = __float2half(vv0);
                        if (gn + 1 < H_) g_xf2h[addr + 184] = __float2half(vv1);
                    }
                } else {                               // MODE 0
                    if (gm >= M || gn >= N) continue;
                    if (GELU) { vv0 = gelu_f(vv0); vv1 = gelu_f(vv1); }
                    if (ADDF) {
                        float2 ad = *(const float2*)&ADD[(long)gm * N + gn];
                        vv0 += ad.x; vv1 += ad.y;
                    }
                    if (WF32) *(float2*)&C[(long)gm * N + gn] = make_float2(vv0, vv1);
                    if (WF16) *(__half2*)&Ch[(long)gm * N + gn] = __floats2half2_rn(vv0, vv1);
                }
            }
        }
    }
}

__global__ void k_dec2(const float* __restrict__ w, float* __restrict__ out) {
    int p = blockIdx.x * blockDim.x + threadIdx.x;
    if (p >= HW) return;
    float a0 = 0.f, a1 = 0.f;
    #pragma unroll 4
    for (int c = 0; c < E_; c++) {
        float v = __half2float(g_t_h[c * HW + p]);
        a0 += w[c] * v;
        a1 += w[E_ + c] * v;
    }
    out[p] = a0;
    out[HW + p] = a1;
}

extern "C" void kernel_launch(void* const* d_in, const int* in_sizes, int n_in,
                              void* d_out, int out_size) {
    const float* x        = (const float*)d_in[0];
    const float* enc_w1   = (const float*)d_in[1];
    const float* enc_w2   = (const float*)d_in[2];
    const float* pos      = (const float*)d_in[3];
    const float* leg_fwd  = (const float*)d_in[4];
    const float* leg_inv  = (const float*)d_in[5];
    const float* w_spec_r = (const float*)d_in[6];
    const float* w_spec_i = (const float*)d_in[7];
    const float* w_inner  = (const float*)d_in[8];
    const float* w_mlp1   = (const float*)d_in[9];
    const float* w_mlp2   = (const float*)d_in[10];
    const float* dec_w1   = (const float*)d_in[11];
    const float* dec_w2   = (const float*)d_in[12];
    float* out = (float*)d_out;

    float *hA, *hB;
    __half *hAh, *hBh, *tH, *wEnc2, *wInn, *wM1, *wM2, *wDec1;
    __half *Fh, *Gih, *xfh, *cfh, *cf2h, *xf2h, *legfH, *legiH, *A2;
    cudaGetSymbolAddress((void**)&hA, g_hA);
    cudaGetSymbolAddress((void**)&hB, g_hB);
    cudaGetSymbolAddress((void**)&hAh, g_hA_h);
    cudaGetSymbolAddress((void**)&hBh, g_hB_h);
    cudaGetSymbolAddress((void**)&tH, g_t_h);
    cudaGetSymbolAddress((void**)&wEnc2, g_w_enc2);
    cudaGetSymbolAddress((void**)&wInn, g_w_inner);
    cudaGetSymbolAddress((void**)&wM1, g_w_mlp1);
    cudaGetSymbolAddress((void**)&wM2, g_w_mlp2);
    cudaGetSymbolAddress((void**)&wDec1, g_w_dec1);
    cudaGetSymbolAddress((void**)&Fh, g_F_h);
    cudaGetSymbolAddress((void**)&Gih, g_Gi_h);
    cudaGetSymbolAddress((void**)&xfh, g_xfh);
    cudaGetSymbolAddress((void**)&cfh, g_cfh);
    cudaGetSymbolAddress((void**)&cf2h, g_cf2h);
    cudaGetSymbolAddress((void**)&xf2h, g_xf2h);
    cudaGetSymbolAddress((void**)&legfH, g_legf_h);
    cudaGetSymbolAddress((void**)&legiH, g_legi_h);
    cudaGetSymbolAddress((void**)&A2, g_A2);

    const int NB = (HW + 127) / 128;   // 507
    dim3 gE(NB, E_ / 128);             // 507 x 2
    dim3 gH(NB, HID_ / 128);           // 507 x 4
    dim3 gRF(2, 360);                  // rfft:   M=46080, N=184
    dim3 gLF(4, 1, MM_);               // legfwd: M=90,    N=512, batch m
    dim3 gSP(1, 4, LM_);               // spectral: M=512, N=96,  batch l
    dim3 gLI(2, 4, MM_);               // leginv: M=512,   N=184, batch m
    dim3 gIR(3, 360);                  // irfft:  M=46080, N=360

    k_init_tables<<<(W_ * 184 + 255) / 256, 256>>>();
    k_zero_cfh<<<(LM_ * 512 * 96 / 8 + 255) / 256, 256>>>();
    k_cast_leg<<<(MM_ * LM_ * 184 + 255) / 256, 256>>>(leg_fwd, legfH);
    k_cast_leg<<<(MM_ * LM_ * 184 + 255) / 256, 256>>>(leg_inv, legiH);
    k_castw<<<(E_ * E_ + 255) / 256, 256>>>(enc_w2, wEnc2, E_ * E_);
    k_castw<<<(NLAY * E_ * E_ + 255) / 256, 256>>>(w_inner, wInn, NLAY * E_ * E_);
    k_castw<<<(NLAY * HID_ * E_ + 255) / 256, 256>>>(w_mlp1, wM1, NLAY * HID_ * E_);
    k_castw<<<(NLAY * E_ * HID_ + 255) / 256, 256>>>(w_mlp2, wM2, NLAY * E_ * HID_);
    k_cast_dec1<<<(E_ * 264 + 255) / 256, 256>>>(dec_w1);
    k_castx<<<(2 * HW + 255) / 256, 256>>>(x);

    k_enc1<<<(HW + 255) / 256, 256>>>(x, enc_w1);
    k_hgemm<0, false, true, true, true><<<gE, 256>>>(wEnc2, hBh, hA, pos, hAh,
                                                     E_, HW, E_, E_, 0, 0, 0);

    for (int i = 0; i < NLAY; i++) {
        // rfft -> g_xfh[m][y][c2]
        k_hgemm<1, false, false, false, false><<<gRF, 256>>>(
            hAh, Fh, nullptr, nullptr, nullptr, 46080, 184, W_, W_, 0, 0, 0);
        // legfwd (batched over m) -> g_cfh[l][c2][m]
        k_hgemm<2, false, false, false, false><<<gLF, 256>>>(
            legfH, xfh, nullptr, nullptr, nullptr, LM_, 512, H_, 184,
            (long)LM_ * 184, (long)H_ * 512, 0);
        // spectral weights + batched spectral GEMM -> g_cf2h[m][o2][l]
        k_buildA2<<<(int)(((long)LM_ * 512 * 256 + 255) / 256), 256>>>(
            w_spec_r + (long)i * E_ * E_ * LM_, w_spec_i + (long)i * E_ * E_ * LM_);
        k_hgemm<3, false, false, false, false><<<gSP, 256>>>(
            A2, cfh, nullptr, nullptr, nullptr, 512, 96, 512, 512,
            (long)512 * 512, (long)512 * 96, 0);
        // leginv (batched over m) -> g_xf2h[(o,y)][2m+ri]
        k_hgemm<4, false, false, false, false><<<gLI, 256>>>(
            cf2h, legiH, nullptr, nullptr, nullptr, 512, 184, LM_, 96,
            (long)512 * 96, (long)LM_ * 184, 0);
        // irfft -> hB fp32
        k_hgemm<0, false, false, true, false><<<gIR, 256>>>(
            xf2h, Gih, hB, nullptr, nullptr, 46080, W_, 182, 184, 0, 0, 0);
        // hB_h = fp16( hB + w_inner @ hA_h )
        k_hgemm<0, false, true, false, true><<<gE, 256>>>(wInn + (long)i * E_ * E_, hAh,
                                                          hB, hB, hBh, E_, HW, E_, E_, 0, 0, 0);
        // t_h = fp16( gelu(w_mlp1 @ hB_h) )
        k_hgemm<0, true, false, false, true><<<gH, 256>>>(wM1 + (long)i * HID_ * E_, hBh,
                                                          hA, nullptr, tH, HID_, HW, E_, E_, 0, 0, 0);
        // hA = w_mlp2 @ t_h + hA ; refresh hA_h
        k_hgemm<0, false, true, true, true><<<gE, 256>>>(wM2 + (long)i * E_ * HID_, tH,
                                                         hA, hA, hAh, E_, HW, HID_, HID_, 0, 0, 0);
    }

    k_hgemm<0, true, false, false, true><<<gE, 256>>>(wDec1, hAh, hA, nullptr,
                                                      tH, E_, HW, 258, 264, 0, 0, 0);
    k_dec2<<<(HW + 255) / 256, 256>>>(dec_w2, out);
}

// round 5
// speedup vs baseline: 5.2280x; 1.0174x over previous
#include <cuda_runtime.h>
#include <cuda_fp16.h>
#include <math.h>

#define HW   64800
#define E_   256
#define NLAY 4
#define LM_  90
#define MM_  91
#define HID_ 512
#define H_   180
#define W_   360
#define STG  4
#define SMEMSZ (STG * (128 * 40 + 32 * 136) * 2)

// ---------------- scratch (device globals) ----------------
__device__ float  g_hA[E_ * HW];           // fp32 h (residual)
__device__ float  g_P [E_ * HW];           // fp32 inner-skip product (side stream)
__device__ __half g_hA_h[(E_ + 2) * HW];   // fp16 h; rows 256,257 = raw x
__device__ __half g_hB_h[E_ * HW];
__device__ __half g_t_h [HID_ * HW];
__device__ __half g_xfh [MM_ * H_ * 512];  // rfft out: [m][y][2c+ri]
__device__ __half g_cfh [LM_ * 512 * 96];  // legfwd out: [l][2c+ri][m] (m pad 96)
__device__ __half g_cf2h[MM_ * 512 * 96];  // spectral out: [m][o2][l] (l pad 96)
__device__ __half g_xf2h[46080 * 184];     // leginv out: [(o,y)][2m+ri] (pad 184)
__device__ __half g_F_h [W_ * 184];        // rfft DFT [x][2m+ri]
__device__ __half g_Gi_h[182 * W_];        // irfft DFT [2m+ri][x]
__device__ __half g_legf_h[MM_ * LM_ * 184 + 64 * 184];
__device__ __half g_legi_h[MM_ * LM_ * 184];
__device__ __half g_A2[NLAY][LM_ * 512 * 512];  // spectral fp16 weights, all layers
// fp16 weights
__device__ __half g_w_enc2[E_ * E_];
__device__ __half g_w_inner[NLAY * E_ * E_];
__device__ __half g_w_mlp1[NLAY * HID_ * E_];
__device__ __half g_w_mlp2[NLAY * E_ * HID_];
__device__ __half g_w_dec1[E_ * 264];

__device__ __forceinline__ float gelu_f(float v) {
    return 0.5f * v * (1.0f + erff(v * 0.7071067811865475f));
}
__device__ __forceinline__ unsigned smem_u32(const void* p) {
    return (unsigned)__cvta_generic_to_shared(p);
}
__device__ __forceinline__ void cp16(void* s, const void* g, bool p) {
    unsigned sa = smem_u32(s);
    asm volatile("cp.async.cg.shared.global [%0],[%1],16,%2;\n"
                 :: "r"(sa), "l"(g), "r"(p ? 16 : 0));
}

// ---------------- DFT tables ----------------
__global__ void k_init_tables() {
    int idx = blockIdx.x * blockDim.x + threadIdx.x;
    if (idx < W_ * 184) {
        int x = idx / 184, col = idx % 184;
        float v = 0.f;
        if (col < 182) {
            int m = col >> 1, ri = col & 1;
            int r = (m * x) % W_;
            double s, c;
            sincospi((double)r / 180.0, &s, &c);
            v = ri ? (float)(-s) : (float)c;
        }
        g_F_h[idx] = __float2half(v);
    }
    if (idx < 182 * W_) {
        int k = idx / W_, x = idx % W_;
        int m = k >> 1, ri = k & 1;
        int r = (m * x) % W_;
        double s, c;
        sincospi((double)r / 180.0, &s, &c);
        double sc = (m == 0) ? (1.0 / 360.0) : (2.0 / 360.0);
        g_Gi_h[idx] = __float2half(ri ? (float)(-sc * s) : (float)(sc * c));
    }
}

__global__ void k_zero_cfh() {
    int i = blockIdx.x * blockDim.x + threadIdx.x;
    if (i < LM_ * 512 * 96 / 8) ((uint4*)g_cfh)[i] = make_uint4(0, 0, 0, 0);
}

__global__ void k_cast_leg(const float* __restrict__ s, __half* __restrict__ d) {
    int i = blockIdx.x * blockDim.x + threadIdx.x;
    if (i >= MM_ * LM_ * 184) return;
    int col = i % 184, row = i / 184;
    d[i] = (col < H_) ? __float2half(s[row * H_ + col]) : __half(0);
}

// spectral fp16 weights for one layer slot
__global__ void k_buildA2(const float* __restrict__ wr, const float* __restrict__ wi, int slot) {
    long idx = (long)blockIdx.x * blockDim.x + threadIdx.x;   // LM*512*256
    if (idx >= (long)LM_ * 512 * 256) return;
    int c  = idx & 255;
    int o2 = (idx >> 8) & 511;
    int l  = idx >> 17;
    int oo = o2 & 255, hi = o2 >> 8;
    long wb = ((long)oo * E_ + c) * LM_ + l;
    float r = wr[wb], im = wi[wb];
    float v0 = hi ? im : r;
    float v1 = hi ? r  : -im;
    *(__half2*)&g_A2[slot][((long)l * 512 + o2) * 512 + 2 * c] = __floats2half2_rn(v0, v1);
}

// ---------------- casts ----------------
__global__ void k_castw(const float* __restrict__ s, __half* __restrict__ d, int n) {
    int i = blockIdx.x * blockDim.x + threadIdx.x;
    if (i < n) d[i] = __float2half(s[i]);
}
__global__ void k_cast_dec1(const float* __restrict__ s) {
    int i = blockIdx.x * blockDim.x + threadIdx.x;
    if (i >= E_ * 264) return;
    int r = i / 264, c = i % 264;
    g_w_dec1[i] = (c < 258) ? __float2half(s[r * 258 + c]) : __half(0);
}
__global__ void k_castx(const float* __restrict__ x) {
    int i = blockIdx.x * blockDim.x + threadIdx.x;
    if (i < 2 * HW) g_hA_h[E_ * HW + i] = __float2half(x[i]);
}

__global__ void k_enc1(const float* __restrict__ x, const float* __restrict__ w) {
    int p = blockIdx.x * blockDim.x + threadIdx.x;
    if (p >= HW) return;
    float x0 = x[p], x1 = x[HW + p];
    #pragma unroll 4
    for (int e = 0; e < E_; e++) {
        float v = w[2 * e] * x0 + w[2 * e + 1] * x1;
        g_hB_h[e * HW + p] = __float2half(gelu_f(v));
    }
}

// ---------------- fp16 tensor-core GEMM, 4-stage cp.async ----------------
// MODE 0: std epilogue. 1: rfft scatter -> g_xfh. 2: legfwd -> g_cfh.
// 3: spectral -> g_cf2h. 4: leginv -> g_xf2h.
template <int MODE, bool GELU, bool ADDF, bool WF32, bool WF16>
__global__ __launch_bounds__(256, 2) void k_hgemm(
    const __half* __restrict__ A, const __half* __restrict__ B,
    float* __restrict__ C, const float* __restrict__ ADD, __half* __restrict__ Ch,
    int M, int N, int K, int lda, long sA, long sB, long sC) {
    extern __shared__ __half dsm[];
    typedef __half (*AsT)[128][40];
    typedef __half (*BsT)[32][136];
    AsT As = (AsT)dsm;
    BsT Bs = (BsT)(dsm + STG * 128 * 40);
    const int tid = threadIdx.x, lane = tid & 31, wid = tid >> 5;
    const int wm = wid >> 2, wn = wid & 3;
    const int bm = blockIdx.y * 128, bn = blockIdx.x * 128;
    const int z = blockIdx.z;
    A += (long)z * sA;
    B += (long)z * sB;
    if (WF32 && MODE == 0) C += (long)z * sC;

    const int r_a = tid >> 1, off_a = (tid & 1) * 16;
    #define LOAD_STAGE(k0, buf)                                                     \
        {                                                                           \
            const __half* pA = A + (long)(bm + r_a) * lda + (k0) + off_a;           \
            bool pa0 = ((k0) + off_a + 8  <= lda);                                  \
            bool pa1 = ((k0) + off_a + 16 <= lda);                                  \
            cp16(&As[buf][r_a][off_a],     pa0 ? pA     : A, pa0);                  \
            cp16(&As[buf][r_a][off_a + 8], pa1 ? pA + 8 : A, pa1);                  \
            _Pragma("unroll")                                                       \
            for (int i = 0; i < 2; i++) {                                           \
                int idx = tid + i * 256;                                            \
                int kk = idx >> 4, noff = (idx & 15) * 8;                           \
                int gk = (k0) + kk, gn = bn + noff;                                 \
                bool pb = (gk < K && gn + 8 <= N);                                  \
                cp16(&Bs[buf][kk][noff], pb ? B + (long)gk * N + gn : B, pb);       \
            }                                                                       \
            asm volatile("cp.async.commit_group;\n" ::);                            \
        }

    float acc[4][4][4];
    #pragma unroll
    for (int i = 0; i < 4; i++)
        #pragma unroll
        for (int j = 0; j < 4; j++)
            #pragma unroll
            for (int q = 0; q < 4; q++) acc[i][j][q] = 0.f;

    LOAD_STAGE(0, 0)
    LOAD_STAGE(32, 1)
    LOAD_STAGE(64, 2)

    const int nslab = (K + 31) / 32;
    for (int it = 0; it < nslab; it++) {
        asm volatile("cp.async.wait_group 2;\n" ::);
        __syncthreads();
        const int buf = it & 3;
        #pragma unroll
        for (int ks = 0; ks < 32; ks += 16) {
            unsigned a[4][4], b[4][2];
            #pragma unroll
            for (int mt = 0; mt < 4; mt++) {
                unsigned addr = smem_u32(&As[buf][wm * 64 + mt * 16 + (lane & 15)][ks + 8 * (lane >> 4)]);
                asm volatile("ldmatrix.sync.aligned.m8n8.x4.shared.b16 {%0,%1,%2,%3},[%4];"
                             : "=r"(a[mt][0]), "=r"(a[mt][1]), "=r"(a[mt][2]), "=r"(a[mt][3])
                             : "r"(addr));
            }
            #pragma unroll
            for (int nt = 0; nt < 4; nt++) {
                unsigned addr = smem_u32(&Bs[buf][ks + (lane & 15)][wn * 32 + nt * 8]);
                asm volatile("ldmatrix.sync.aligned.m8n8.x2.trans.shared.b16 {%0,%1},[%2];"
                             : "=r"(b[nt][0]), "=r"(b[nt][1])
                             : "r"(addr));
            }
            #pragma unroll
            for (int mt = 0; mt < 4; mt++)
                #pragma unroll
                for (int nt = 0; nt < 4; nt++)
                    asm volatile(
                        "mma.sync.aligned.m16n8k16.row.col.f32.f16.f16.f32 "
                        "{%0,%1,%2,%3},{%4,%5,%6,%7},{%8,%9},{%0,%1,%2,%3};"
                        : "+f"(acc[mt][nt][0]), "+f"(acc[mt][nt][1]),
                          "+f"(acc[mt][nt][2]), "+f"(acc[mt][nt][3])
                        : "r"(a[mt][0]), "r"(a[mt][1]), "r"(a[mt][2]), "r"(a[mt][3]),
                          "r"(b[nt][0]), "r"(b[nt][1]));
        }
        __syncthreads();
        int k0n = (it + 3) * 32;
        if (k0n < K) {
            LOAD_STAGE(k0n, (it + 3) & 3)
        } else {
            asm volatile("cp.async.commit_group;\n" ::);
        }
    }
    #undef LOAD_STAGE

    // ---------------- epilogue ----------------
    const int g = lane >> 2, tq = lane & 3;
    #pragma unroll
    for (int mt = 0; mt < 4; mt++) {
        #pragma unroll
        for (int hh = 0; hh < 2; hh++) {
            int gm = bm + wm * 64 + mt * 16 + g + hh * 8;
            float vv0, vv1;
            #pragma unroll
            for (int nt = 0; nt < 4; nt++) {
                int gn = bn + wn * 32 + nt * 8 + tq * 2;
                vv0 = acc[mt][nt][hh * 2 + 0];
                vv1 = acc[mt][nt][hh * 2 + 1];
                if (MODE == 1) {                       // rfft: gn = 2m(+1)
                    if (gn < 2 * MM_) {
                        int m = gn >> 1;
                        int c = gm / H_, y = gm - c * H_;
                        *(__half2*)&g_xfh[(long)m * (H_ * 512) + y * 512 + 2 * c] =
                            __floats2half2_rn(vv0, vv1);
                    }
                } else if (MODE == 2) {                // legfwd: gm=l, gn=c2, z=m
                    if (gm < LM_) {
                        long base = ((long)gm * 512 + gn) * 96 + z;
                        g_cfh[base]      = __float2half(vv0);
                        g_cfh[base + 96] = __float2half(vv1);
                    }
                } else if (MODE == 3) {                // spectral: gm=o2, gn=m, z=l
                    if (gn < MM_)
                        g_cf2h[((long)gn * 512 + gm) * 96 + z] = __float2half(vv0);
                    if (gn + 1 < MM_)
                        g_cf2h[((long)(gn + 1) * 512 + gm) * 96 + z] = __float2half(vv1);
                } else if (MODE == 4) {                // leginv: gm=o2, gn=h, z=m
                    int oo = gm & 255, ri = gm >> 8;
                    if (gn < H_) {
                        long addr = ((long)oo * H_ + gn) * 184 + 2 * z + ri;
                        g_xf2h[addr] = __float2half(vv0);
                        if (gn + 1 < H_) g_xf2h[addr + 184] = __float2half(vv1);
                    }
                } else {                               // MODE 0
                    if (gm >= M || gn >= N) continue;
                    if (GELU) { vv0 = gelu_f(vv0); vv1 = gelu_f(vv1); }
                    if (ADDF) {
                        float2 ad = *(const float2*)&ADD[(long)gm * N + gn];
                        vv0 += ad.x; vv1 += ad.y;
                    }
                    if (WF32) *(float2*)&C[(long)gm * N + gn] = make_float2(vv0, vv1);
                    if (WF16) *(__half2*)&Ch[(long)gm * N + gn] = __floats2half2_rn(vv0, vv1);
                }
            }
        }
    }
}

__global__ void k_dec2(const float* __restrict__ w, float* __restrict__ out) {
    int p = blockIdx.x * blockDim.x + threadIdx.x;
    if (p >= HW) return;
    float a0 = 0.f, a1 = 0.f;
    #pragma unroll 4
    for (int c = 0; c < E_; c++) {
        float v = __half2float(g_t_h[c * HW + p]);
        a0 += w[c] * v;
        a1 += w[E_ + c] * v;
    }
    out[p] = a0;
    out[HW + p] = a1;
}

extern "C" void kernel_launch(void* const* d_in, const int* in_sizes, int n_in,
                              void* d_out, int out_size) {
    const float* x        = (const float*)d_in[0];
    const float* enc_w1   = (const float*)d_in[1];
    const float* enc_w2   = (const float*)d_in[2];
    const float* pos      = (const float*)d_in[3];
    const float* leg_fwd  = (const float*)d_in[4];
    const float* leg_inv  = (const float*)d_in[5];
    const float* w_spec_r = (const float*)d_in[6];
    const float* w_spec_i = (const float*)d_in[7];
    const float* w_inner  = (const float*)d_in[8];
    const float* w_mlp1   = (const float*)d_in[9];
    const float* w_mlp2   = (const float*)d_in[10];
    const float* dec_w1   = (const float*)d_in[11];
    const float* dec_w2   = (const float*)d_in[12];
    float* out = (float*)d_out;

    float *hA, *Pf;
    __half *hAh, *hBh, *tH, *wEnc2, *wInn, *wM1, *wM2, *wDec1;
    __half *Fh, *Gih, *xfh, *cfh, *cf2h, *xf2h, *legfH, *legiH, *A2;
    cudaGetSymbolAddress((void**)&hA, g_hA);
    cudaGetSymbolAddress((void**)&Pf, g_P);
    cudaGetSymbolAddress((void**)&hAh, g_hA_h);
    cudaGetSymbolAddress((void**)&hBh, g_hB_h);
    cudaGetSymbolAddress((void**)&tH, g_t_h);
    cudaGetSymbolAddress((void**)&wEnc2, g_w_enc2);
    cudaGetSymbolAddress((void**)&wInn, g_w_inner);
    cudaGetSymbolAddress((void**)&wM1, g_w_mlp1);
    cudaGetSymbolAddress((void**)&wM2, g_w_mlp2);
    cudaGetSymbolAddress((void**)&wDec1, g_w_dec1);
    cudaGetSymbolAddress((void**)&Fh, g_F_h);
    cudaGetSymbolAddress((void**)&Gih, g_Gi_h);
    cudaGetSymbolAddress((void**)&xfh, g_xfh);
    cudaGetSymbolAddress((void**)&cfh, g_cfh);
    cudaGetSymbolAddress((void**)&cf2h, g_cf2h);
    cudaGetSymbolAddress((void**)&xf2h, g_xf2h);
    cudaGetSymbolAddress((void**)&legfH, g_legf_h);
    cudaGetSymbolAddress((void**)&legiH, g_legi_h);
    cudaGetSymbolAddress((void**)&A2, g_A2);

    // opt-in dynamic smem for every instantiation used
    cudaFuncSetAttribute(k_hgemm<0, false, true,  true,  true >, cudaFuncAttributeMaxDynamicSharedMemorySize, SMEMSZ);
    cudaFuncSetAttribute(k_hgemm<0, false, true,  false, true >, cudaFuncAttributeMaxDynamicSharedMemorySize, SMEMSZ);
    cudaFuncSetAttribute(k_hgemm<0, true,  false, false, true >, cudaFuncAttributeMaxDynamicSharedMemorySize, SMEMSZ);
    cudaFuncSetAttribute(k_hgemm<0, false, false, true,  false>, cudaFuncAttributeMaxDynamicSharedMemorySize, SMEMSZ);
    cudaFuncSetAttribute(k_hgemm<1, false, false, false, false>, cudaFuncAttributeMaxDynamicSharedMemorySize, SMEMSZ);
    cudaFuncSetAttribute(k_hgemm<2, false, false, false, false>, cudaFuncAttributeMaxDynamicSharedMemorySize, SMEMSZ);
    cudaFuncSetAttribute(k_hgemm<3, false, false, false, false>, cudaFuncAttributeMaxDynamicSharedMemorySize, SMEMSZ);
    cudaFuncSetAttribute(k_hgemm<4, false, false, false, false>, cudaFuncAttributeMaxDynamicSharedMemorySize, SMEMSZ);

    // side stream + events (lazy one-time resource init; work is identical every call)
    static cudaStream_t sd = nullptr;
    static cudaEvent_t evRoot, evA2, evL[NLAY], evP[NLAY];
    if (!sd) {
        cudaStreamCreateWithFlags(&sd, cudaStreamNonBlocking);
        cudaEventCreateWithFlags(&evRoot, cudaEventDisableTiming);
        cudaEventCreateWithFlags(&evA2, cudaEventDisableTiming);
        for (int i = 0; i < NLAY; i++) {
            cudaEventCreateWithFlags(&evL[i], cudaEventDisableTiming);
            cudaEventCreateWithFlags(&evP[i], cudaEventDisableTiming);
        }
    }

    const int NB = (HW + 127) / 128;   // 507
    dim3 gE(NB, E_ / 128);             // 507 x 2
    dim3 gH(NB, HID_ / 128);           // 507 x 4
    dim3 gRF(2, 360);                  // rfft
    dim3 gLF(4, 1, MM_);               // legfwd
    dim3 gSP(1, 4, LM_);               // spectral
    dim3 gLI(2, 4, MM_);               // leginv
    dim3 gIR(3, 360);                  // irfft

    // ---- fork side stream; build all spectral weight slabs there ----
    cudaEventRecord(evRoot, 0);
    cudaStreamWaitEvent(sd, evRoot, 0);
    for (int i = 0; i < NLAY; i++)
        k_buildA2<<<(int)(((long)LM_ * 512 * 256 + 255) / 256), 256, 0, sd>>>(
            w_spec_r + (long)i * E_ * E_ * LM_, w_spec_i + (long)i * E_ * E_ * LM_, i);
    cudaEventRecord(evA2, sd);

    // ---- main: tables + casts + encoder ----
    k_init_tables<<<(W_ * 184 + 255) / 256, 256>>>();
    k_zero_cfh<<<(LM_ * 512 * 96 / 8 + 255) / 256, 256>>>();
    k_cast_leg<<<(MM_ * LM_ * 184 + 255) / 256, 256>>>(leg_fwd, legfH);
    k_cast_leg<<<(MM_ * LM_ * 184 + 255) / 256, 256>>>(leg_inv, legiH);
    k_castw<<<(E_ * E_ + 255) / 256, 256>>>(enc_w2, wEnc2, E_ * E_);
    k_castw<<<(NLAY * E_ * E_ + 255) / 256, 256>>>(w_inner, wInn, NLAY * E_ * E_);
    k_castw<<<(NLAY * HID_ * E_ + 255) / 256, 256>>>(w_mlp1, wM1, NLAY * HID_ * E_);
    k_castw<<<(NLAY * E_ * HID_ + 255) / 256, 256>>>(w_mlp2, wM2, NLAY * E_ * HID_);
    k_cast_dec1<<<(E_ * 264 + 255) / 256, 256>>>(dec_w1);
    k_castx<<<(2 * HW + 255) / 256, 256>>>(x);

    k_enc1<<<(HW + 255) / 256, 256>>>(x, enc_w1);
    k_hgemm<0, false, true, true, true><<<gE, 256, SMEMSZ>>>(wEnc2, hBh, hA, pos, hAh,
                                                             E_, HW, E_, E_, 0, 0, 0);
    cudaEventRecord(evL[0], 0);

    for (int i = 0; i < NLAY; i++) {
        // side: P = w_inner[i] @ hAh (fp32), concurrent with spectral chain
        cudaStreamWaitEvent(sd, evL[i], 0);
        k_hgemm<0, false, false, true, false><<<gE, 256, SMEMSZ, sd>>>(
            wInn + (long)i * E_ * E_, hAh, Pf, nullptr, nullptr, E_, HW, E_, E_, 0, 0, 0);
        cudaEventRecord(evP[i], sd);

        // main: spectral chain
        k_hgemm<1, false, false, false, false><<<gRF, 256, SMEMSZ>>>(
            hAh, Fh, nullptr, nullptr, nullptr, 46080, 184, W_, W_, 0, 0, 0);
        k_hgemm<2, false, false, false, false><<<gLF, 256, SMEMSZ>>>(
            legfH, xfh, nullptr, nullptr, nullptr, LM_, 512, H_, 184,
            (long)LM_ * 184, (long)H_ * 512, 0);
        if (i == 0) cudaStreamWaitEvent(0, evA2, 0);
        k_hgemm<3, false, false, false, false><<<gSP, 256, SMEMSZ>>>(
            A2 + (long)i * LM_ * 512 * 512, cfh, nullptr, nullptr, nullptr, 512, 96, 512, 512,
            (long)512 * 512, (long)512 * 96, 0);
        k_hgemm<4, false, false, false, false><<<gLI, 256, SMEMSZ>>>(
            cf2h, legiH, nullptr, nullptr, nullptr, 512, 184, LM_, 96,
            (long)512 * 96, (long)LM_ * 184, 0);
        // irfft + inner skip fused: hBh = fp16( irfft(xf2h) + P )
        cudaStreamWaitEvent(0, evP[i], 0);
        k_hgemm<0, false, true, false, true><<<gIR, 256, SMEMSZ>>>(
            xf2h, Gih, nullptr, Pf, hBh, 46080, W_, 182, 184, 0, 0, 0);
        // t_h = fp16( gelu(w_mlp1 @ hBh) )
        k_hgemm<0, true, false, false, true><<<gH, 256, SMEMSZ>>>(
            wM1 + (long)i * HID_ * E_, hBh, hA, nullptr, tH, HID_, HW, E_, E_, 0, 0, 0);
        // hA = w_mlp2 @ t_h + hA ; refresh hAh
        k_hgemm<0, false, true, true, true><<<gE, 256, SMEMSZ>>>(
            wM2 + (long)i * E_ * HID_, tH, hA, hA, hAh, E_, HW, HID_, HID_, 0, 0, 0);
        if (i + 1 < NLAY) cudaEventRecord(evL[i + 1], 0);
    }

    k_hgemm<0, true, false, false, true><<<gE, 256, SMEMSZ>>>(wDec1, hAh, hA, nullptr,
                                                              tH, E_, HW, 258, 264, 0, 0, 0);
    k_dec2<<<(HW + 255) / 256, 256>>>(dec_w2, out);
}

// round 6
// speedup vs baseline: 5.8650x; 1.1219x over previous
#include <cuda_runtime.h>
#include <cuda_fp16.h>
#include <math.h>

#define HW   64800
#define E_   256
#define NLAY 4
#define LM_  90
#define MM_  91
#define HID_ 512
#define H_   180
#define W_   360
#define STG  4
#define SMEMSZ (STG * (128 * 40 + 32 * 136) * 2)

// ---------------- scratch (device globals) ----------------
__device__ float  g_hA[E_ * HW];           // fp32 h (residual)
__device__ float  g_P [E_ * HW];           // fp32 inner-skip product (side stream)
__device__ __half g_hA_h[(E_ + 2) * HW];   // fp16 h; rows 256,257 = raw x
__device__ __half g_hB_h[E_ * HW];
__device__ __half g_t_h [HID_ * HW];
__device__ __half g_xfh [MM_ * H_ * 512];  // rfft out: [m][y][2c+ri]
__device__ __half g_cfh [LM_ * 512 * 96];  // legfwd out: [l][2c+ri][m] (m pad 96)
__device__ __half g_cf2h[MM_ * 512 * 96];  // spectral out: [m][o2][l] (l pad 96)
__device__ __half g_xf2h[46080 * 184];     // leginv out: [(o,y)][2m+ri] (pad 184)
__device__ __half g_F_h [W_ * 184];        // rfft DFT [x][2m+ri]
__device__ __half g_Gi_h[182 * W_];        // irfft DFT [2m+ri][x]
__device__ __half g_legf_h[MM_ * LM_ * 184 + 64 * 184];
__device__ __half g_legi_h[MM_ * LM_ * 184];
__device__ __half g_A2[NLAY][LM_ * 512 * 512];  // spectral fp16 weights, all layers
// fp16 weights
__device__ __half g_w_enc2[E_ * E_];
__device__ __half g_w_inner[NLAY * E_ * E_];
__device__ __half g_w_mlp1[NLAY * HID_ * E_];
__device__ __half g_w_mlp2[NLAY * E_ * HID_];
__device__ __half g_w_dec1[E_ * 264];

__device__ __forceinline__ float gelu_f(float v) {
    return 0.5f * v * (1.0f + erff(v * 0.7071067811865475f));
}
__device__ __forceinline__ unsigned smem_u32(const void* p) {
    return (unsigned)__cvta_generic_to_shared(p);
}
__device__ __forceinline__ void cp16(void* s, const void* g, bool p) {
    unsigned sa = smem_u32(s);
    asm volatile("cp.async.cg.shared.global [%0],[%1],16,%2;\n"
                 :: "r"(sa), "l"(g), "r"(p ? 16 : 0));
}

// ---------------- DFT tables ----------------
__global__ void k_init_tables() {
    int idx = blockIdx.x * blockDim.x + threadIdx.x;
    if (idx < W_ * 184) {
        int x = idx / 184, col = idx % 184;
        float v = 0.f;
        if (col < 182) {
            int m = col >> 1, ri = col & 1;
            int r = (m * x) % W_;
            double s, c;
            sincospi((double)r / 180.0, &s, &c);
            v = ri ? (float)(-s) : (float)c;
        }
        g_F_h[idx] = __float2half(v);
    }
    if (idx < 182 * W_) {
        int k = idx / W_, x = idx % W_;
        int m = k >> 1, ri = k & 1;
        int r = (m * x) % W_;
        double s, c;
        sincospi((double)r / 180.0, &s, &c);
        double sc = (m == 0) ? (1.0 / 360.0) : (2.0 / 360.0);
        g_Gi_h[idx] = __float2half(ri ? (float)(-sc * s) : (float)(sc * c));
    }
}

__global__ void k_zero_cfh() {
    int i = blockIdx.x * blockDim.x + threadIdx.x;
    if (i < LM_ * 512 * 96 / 8) ((uint4*)g_cfh)[i] = make_uint4(0, 0, 0, 0);
}

__global__ void k_cast_leg(const float* __restrict__ s, __half* __restrict__ d) {
    int i = blockIdx.x * blockDim.x + threadIdx.x;
    if (i >= MM_ * LM_ * 184) return;
    int col = i % 184, row = i / 184;
    d[i] = (col < H_) ? __float2half(s[row * H_ + col]) : __half(0);
}

// transpose-tiled spectral weight build: coalesced reads along l, coalesced writes along c
__global__ void k_buildA2_t(const float* __restrict__ wr, const float* __restrict__ wi, int slot) {
    int o  = blockIdx.z;           // 0..255
    int c0 = blockIdx.x * 32;      // 0..224
    int l0 = blockIdx.y * 32;      // 0,32,64
    __shared__ float sr[32][33], si[32][33];
    int tx = threadIdx.x, ty = threadIdx.y;  // 32 x 8
    #pragma unroll
    for (int i = 0; i < 32; i += 8) {
        int c = c0 + ty + i, l = l0 + tx;
        long base = ((long)o * E_ + c) * LM_ + l;
        bool ok = (l < LM_);
        sr[ty + i][tx] = ok ? wr[base] : 0.f;
        si[ty + i][tx] = ok ? wi[base] : 0.f;
    }
    __syncthreads();
    int c = c0 + tx;
    #pragma unroll
    for (int j = 0; j < 32; j += 8) {
        int l = l0 + ty + j;
        if (l >= LM_) break;
        float r  = sr[tx][ty + j];
        float im = si[tx][ty + j];
        long b0 = ((long)l * 512 + o) * 512 + 2 * c;
        long b1 = ((long)l * 512 + o + 256) * 512 + 2 * c;
        *(__half2*)&g_A2[slot][b0] = __floats2half2_rn(r, -im);   // real-out row
        *(__half2*)&g_A2[slot][b1] = __floats2half2_rn(im, r);    // imag-out row
    }
}

// ---------------- casts ----------------
__global__ void k_castw(const float* __restrict__ s, __half* __restrict__ d, int n) {
    int i = blockIdx.x * blockDim.x + threadIdx.x;
    if (i < n) d[i] = __float2half(s[i]);
}
__global__ void k_cast_dec1(const float* __restrict__ s) {
    int i = blockIdx.x * blockDim.x + threadIdx.x;
    if (i >= E_ * 264) return;
    int r = i / 264, c = i % 264;
    g_w_dec1[i] = (c < 258) ? __float2half(s[r * 258 + c]) : __half(0);
}
__global__ void k_castx(const float* __restrict__ x) {
    int i = blockIdx.x * blockDim.x + threadIdx.x;
    if (i < 2 * HW) g_hA_h[E_ * HW + i] = __float2half(x[i]);
}

__global__ void k_enc1(const float* __restrict__ x, const float* __restrict__ w) {
    int p = blockIdx.x * blockDim.x + threadIdx.x;
    if (p >= HW) return;
    float x0 = x[p], x1 = x[HW + p];
    #pragma unroll 4
    for (int e = 0; e < E_; e++) {
        float v = w[2 * e] * x0 + w[2 * e + 1] * x1;
        g_hB_h[e * HW + p] = __float2half(gelu_f(v));
    }
}

// ---------------- fp16 tensor-core GEMM, 4-stage cp.async ----------------
// MODE 0: std epilogue. 1: rfft scatter -> g_xfh. 2: legfwd -> g_cfh.
// 3: spectral -> g_cf2h. 4: leginv -> g_xf2h.
template <int MODE, bool GELU, bool ADDF, bool WF32, bool WF16>
__global__ __launch_bounds__(256, 2) void k_hgemm(
    const __half* __restrict__ A, const __half* __restrict__ B,
    float* __restrict__ C, const float* __restrict__ ADD, __half* __restrict__ Ch,
    int M, int N, int K, int lda, long sA, long sB, long sC) {
    extern __shared__ __half dsm[];
    typedef __half (*AsT)[128][40];
    typedef __half (*BsT)[32][136];
    AsT As = (AsT)dsm;
    BsT Bs = (BsT)(dsm + STG * 128 * 40);
    const int tid = threadIdx.x, lane = tid & 31, wid = tid >> 5;
    const int wm = wid >> 2, wn = wid & 3;
    const int bm = blockIdx.y * 128, bn = blockIdx.x * 128;
    const int z = blockIdx.z;
    A += (long)z * sA;
    B += (long)z * sB;
    if (WF32 && MODE == 0) C += (long)z * sC;

    const int r_a = tid >> 1, off_a = (tid & 1) * 16;
    #define LOAD_STAGE(k0, buf)                                                     \
        {                                                                           \
            const __half* pA = A + (long)(bm + r_a) * lda + (k0) + off_a;           \
            bool pa0 = ((k0) + off_a + 8  <= lda);                                  \
            bool pa1 = ((k0) + off_a + 16 <= lda);                                  \
            cp16(&As[buf][r_a][off_a],     pa0 ? pA     : A, pa0);                  \
            cp16(&As[buf][r_a][off_a + 8], pa1 ? pA + 8 : A, pa1);                  \
            _Pragma("unroll")                                                       \
            for (int i = 0; i < 2; i++) {                                           \
                int idx = tid + i * 256;                                            \
                int kk = idx >> 4, noff = (idx & 15) * 8;                           \
                int gk = (k0) + kk, gn = bn + noff;                                 \
                bool pb = (gk < K && gn + 8 <= N);                                  \
                cp16(&Bs[buf][kk][noff], pb ? B + (long)gk * N + gn : B, pb);       \
            }                                                                       \
            asm volatile("cp.async.commit_group;\n" ::);                            \
        }

    float acc[4][4][4];
    #pragma unroll
    for (int i = 0; i < 4; i++)
        #pragma unroll
        for (int j = 0; j < 4; j++)
            #pragma unroll
            for (int q = 0; q < 4; q++) acc[i][j][q] = 0.f;

    LOAD_STAGE(0, 0)
    LOAD_STAGE(32, 1)
    LOAD_STAGE(64, 2)

    const int nslab = (K + 31) / 32;
    for (int it = 0; it < nslab; it++) {
        asm volatile("cp.async.wait_group 2;\n" ::);
        __syncthreads();
        const int buf = it & 3;
        #pragma unroll
        for (int ks = 0; ks < 32; ks += 16) {
            unsigned a[4][4], b[4][2];
            #pragma unroll
            for (int mt = 0; mt < 4; mt++) {
                unsigned addr = smem_u32(&As[buf][wm * 64 + mt * 16 + (lane & 15)][ks + 8 * (lane >> 4)]);
                asm volatile("ldmatrix.sync.aligned.m8n8.x4.shared.b16 {%0,%1,%2,%3},[%4];"
                             : "=r"(a[mt][0]), "=r"(a[mt][1]), "=r"(a[mt][2]), "=r"(a[mt][3])
                             : "r"(addr));
            }
            #pragma unroll
            for (int nt = 0; nt < 4; nt++) {
                unsigned addr = smem_u32(&Bs[buf][ks + (lane & 15)][wn * 32 + nt * 8]);
                asm volatile("ldmatrix.sync.aligned.m8n8.x2.trans.shared.b16 {%0,%1},[%2];"
                             : "=r"(b[nt][0]), "=r"(b[nt][1])
                             : "r"(addr));
            }
            #pragma unroll
            for (int mt = 0; mt < 4; mt++)
                #pragma unroll
                for (int nt = 0; nt < 4; nt++)
                    asm volatile(
                        "mma.sync.aligned.m16n8k16.row.col.f32.f16.f16.f32 "
                        "{%0,%1,%2,%3},{%4,%5,%6,%7},{%8,%9},{%0,%1,%2,%3};"
                        : "+f"(acc[mt][nt][0]), "+f"(acc[mt][nt][1]),
                          "+f"(acc[mt][nt][2]), "+f"(acc[mt][nt][3])
                        : "r"(a[mt][0]), "r"(a[mt][1]), "r"(a[mt][2]), "r"(a[mt][3]),
                          "r"(b[nt][0]), "r"(b[nt][1]));
        }
        __syncthreads();
        int k0n = (it + 3) * 32;
        if (k0n < K) {
            LOAD_STAGE(k0n, (it + 3) & 3)
        } else {
            asm volatile("cp.async.commit_group;\n" ::);
        }
    }
    #undef LOAD_STAGE

    // ---------------- epilogue ----------------
    const int g = lane >> 2, tq = lane & 3;
    #pragma unroll
    for (int mt = 0; mt < 4; mt++) {
        #pragma unroll
        for (int hh = 0; hh < 2; hh++) {
            int gm = bm + wm * 64 + mt * 16 + g + hh * 8;
            float vv0, vv1;
            #pragma unroll
            for (int nt = 0; nt < 4; nt++) {
                int gn = bn + wn * 32 + nt * 8 + tq * 2;
                vv0 = acc[mt][nt][hh * 2 + 0];
                vv1 = acc[mt][nt][hh * 2 + 1];
                if (MODE == 1) {
                    if (gn < 2 * MM_) {
                        int m = gn >> 1;
                        int c = gm / H_, y = gm - c * H_;
                        *(__half2*)&g_xfh[(long)m * (H_ * 512) + y * 512 + 2 * c] =
                            __floats2half2_rn(vv0, vv1);
                    }
                } else if (MODE == 2) {
                    if (gm < LM_) {
                        long base = ((long)gm * 512 + gn) * 96 + z;
                        g_cfh[base]      = __float2half(vv0);
                        g_cfh[base + 96] = __float2half(vv1);
                    }
                } else if (MODE == 3) {
                    if (gn < MM_)
                        g_cf2h[((long)gn * 512 + gm) * 96 + z] = __float2half(vv0);
                    if (gn + 1 < MM_)
                        g_cf2h[((long)(gn + 1) * 512 + gm) * 96 + z] = __float2half(vv1);
                } else if (MODE == 4) {
                    int oo = gm & 255, ri = gm >> 8;
                    if (gn < H_) {
                        long addr = ((long)oo * H_ + gn) * 184 + 2 * z + ri;
                        g_xf2h[addr] = __float2half(vv0);
                        if (gn + 1 < H_) g_xf2h[addr + 184] = __float2half(vv1);
                    }
                } else {
                    if (gm >= M || gn >= N) continue;
                    if (GELU) { vv0 = gelu_f(vv0); vv1 = gelu_f(vv1); }
                    if (ADDF) {
                        float2 ad = *(const float2*)&ADD[(long)gm * N + gn];
                        vv0 += ad.x; vv1 += ad.y;
                    }
                    if (WF32) *(float2*)&C[(long)gm * N + gn] = make_float2(vv0, vv1);
                    if (WF16) *(__half2*)&Ch[(long)gm * N + gn] = __floats2half2_rn(vv0, vv1);
                }
            }
        }
    }
}

__global__ void k_dec2(const float* __restrict__ w, float* __restrict__ out) {
    int p = blockIdx.x * blockDim.x + threadIdx.x;
    if (p >= HW) return;
    float a0 = 0.f, a1 = 0.f;
    #pragma unroll 4
    for (int c = 0; c < E_; c++) {
        float v = __half2float(g_t_h[c * HW + p]);
        a0 += w[c] * v;
        a1 += w[E_ + c] * v;
    }
    out[p] = a0;
    out[HW + p] = a1;
}

extern "C" void kernel_launch(void* const* d_in, const int* in_sizes, int n_in,
                              void* d_out, int out_size) {
    const float* x        = (const float*)d_in[0];
    const float* enc_w1   = (const float*)d_in[1];
    const float* enc_w2   = (const float*)d_in[2];
    const float* pos      = (const float*)d_in[3];
    const float* leg_fwd  = (const float*)d_in[4];
    const float* leg_inv  = (const float*)d_in[5];
    const float* w_spec_r = (const float*)d_in[6];
    const float* w_spec_i = (const float*)d_in[7];
    const float* w_inner  = (const float*)d_in[8];
    const float* w_mlp1   = (const float*)d_in[9];
    const float* w_mlp2   = (const float*)d_in[10];
    const float* dec_w1   = (const float*)d_in[11];
    const float* dec_w2   = (const float*)d_in[12];
    float* out = (float*)d_out;

    float *hA, *Pf;
    __half *hAh, *hBh, *tH, *wEnc2, *wInn, *wM1, *wM2, *wDec1;
    __half *Fh, *Gih, *xfh, *cfh, *cf2h, *xf2h, *legfH, *legiH, *A2;
    cudaGetSymbolAddress((void**)&hA, g_hA);
    cudaGetSymbolAddress((void**)&Pf, g_P);
    cudaGetSymbolAddress((void**)&hAh, g_hA_h);
    cudaGetSymbolAddress((void**)&hBh, g_hB_h);
    cudaGetSymbolAddress((void**)&tH, g_t_h);
    cudaGetSymbolAddress((void**)&wEnc2, g_w_enc2);
    cudaGetSymbolAddress((void**)&wInn, g_w_inner);
    cudaGetSymbolAddress((void**)&wM1, g_w_mlp1);
    cudaGetSymbolAddress((void**)&wM2, g_w_mlp2);
    cudaGetSymbolAddress((void**)&wDec1, g_w_dec1);
    cudaGetSymbolAddress((void**)&Fh, g_F_h);
    cudaGetSymbolAddress((void**)&Gih, g_Gi_h);
    cudaGetSymbolAddress((void**)&xfh, g_xfh);
    cudaGetSymbolAddress((void**)&cfh, g_cfh);
    cudaGetSymbolAddress((void**)&cf2h, g_cf2h);
    cudaGetSymbolAddress((void**)&xf2h, g_xf2h);
    cudaGetSymbolAddress((void**)&legfH, g_legf_h);
    cudaGetSymbolAddress((void**)&legiH, g_legi_h);
    cudaGetSymbolAddress((void**)&A2, g_A2);

    cudaFuncSetAttribute(k_hgemm<0, false, true,  true,  true >, cudaFuncAttributeMaxDynamicSharedMemorySize, SMEMSZ);
    cudaFuncSetAttribute(k_hgemm<0, false, true,  false, true >, cudaFuncAttributeMaxDynamicSharedMemorySize, SMEMSZ);
    cudaFuncSetAttribute(k_hgemm<0, true,  false, false, true >, cudaFuncAttributeMaxDynamicSharedMemorySize, SMEMSZ);
    cudaFuncSetAttribute(k_hgemm<0, false, false, true,  false>, cudaFuncAttributeMaxDynamicSharedMemorySize, SMEMSZ);
    cudaFuncSetAttribute(k_hgemm<1, false, false, false, false>, cudaFuncAttributeMaxDynamicSharedMemorySize, SMEMSZ);
    cudaFuncSetAttribute(k_hgemm<2, false, false, false, false>, cudaFuncAttributeMaxDynamicSharedMemorySize, SMEMSZ);
    cudaFuncSetAttribute(k_hgemm<3, false, false, false, false>, cudaFuncAttributeMaxDynamicSharedMemorySize, SMEMSZ);
    cudaFuncSetAttribute(k_hgemm<4, false, false, false, false>, cudaFuncAttributeMaxDynamicSharedMemorySize, SMEMSZ);

    static cudaStream_t s1 = nullptr, s2 = nullptr;  // s1: init + builds, s2: inner GEMMs
    static cudaEvent_t evRoot, evInit, evA2[NLAY], evL[NLAY], evP[NLAY];
    if (!s1) {
        cudaStreamCreateWithFlags(&s1, cudaStreamNonBlocking);
        cudaStreamCreateWithFlags(&s2, cudaStreamNonBlocking);
        cudaEventCreateWithFlags(&evRoot, cudaEventDisableTiming);
        cudaEventCreateWithFlags(&evInit, cudaEventDisableTiming);
        for (int i = 0; i < NLAY; i++) {
            cudaEventCreateWithFlags(&evA2[i], cudaEventDisableTiming);
            cudaEventCreateWithFlags(&evL[i], cudaEventDisableTiming);
            cudaEventCreateWithFlags(&evP[i], cudaEventDisableTiming);
        }
    }

    const int NB = (HW + 127) / 128;   // 507
    dim3 gE(NB, E_ / 128);
    dim3 gH(NB, HID_ / 128);
    dim3 gRF(2, 360);
    dim3 gLF(4, 1, MM_);
    dim3 gSP(1, 4, LM_);
    dim3 gLI(2, 4, MM_);
    dim3 gIR(3, 360);
    dim3 gB2(8, 3, 256), bB2(32, 8);

    // ---- fork init stream ----
    cudaEventRecord(evRoot, 0);
    cudaStreamWaitEvent(s1, evRoot, 0);
    k_castw<<<(NLAY * E_ * E_ + 255) / 256, 256, 0, s1>>>(w_inner, wInn, NLAY * E_ * E_);
    k_castw<<<(NLAY * HID_ * E_ + 255) / 256, 256, 0, s1>>>(w_mlp1, wM1, NLAY * HID_ * E_);
    k_castw<<<(NLAY * E_ * HID_ + 255) / 256, 256, 0, s1>>>(w_mlp2, wM2, NLAY * E_ * HID_);
    k_init_tables<<<(W_ * 184 + 255) / 256, 256, 0, s1>>>();
    k_zero_cfh<<<(LM_ * 512 * 96 / 8 + 255) / 256, 256, 0, s1>>>();
    k_cast_leg<<<(MM_ * LM_ * 184 + 255) / 256, 256, 0, s1>>>(leg_fwd, legfH);
    k_cast_leg<<<(MM_ * LM_ * 184 + 255) / 256, 256, 0, s1>>>(leg_inv, legiH);
    k_cast_dec1<<<(E_ * 264 + 255) / 256, 256, 0, s1>>>(dec_w1);
    k_castx<<<(2 * HW + 255) / 256, 256, 0, s1>>>(x);
    cudaEventRecord(evInit, s1);
    for (int i = 0; i < NLAY; i++) {
        k_buildA2_t<<<gB2, bB2, 0, s1>>>(w_spec_r + (long)i * E_ * E_ * LM_,
                                         w_spec_i + (long)i * E_ * E_ * LM_, i);
        cudaEventRecord(evA2[i], s1);
    }

    // ---- main: encoder ----
    k_castw<<<(E_ * E_ + 255) / 256, 256>>>(enc_w2, wEnc2, E_ * E_);
    k_enc1<<<(HW + 255) / 256, 256>>>(x, enc_w1);
    k_hgemm<0, false, true, true, true><<<gE, 256, SMEMSZ>>>(wEnc2, hBh, hA, pos, hAh,
                                                             E_, HW, E_, E_, 0, 0, 0);
    cudaEventRecord(evL[0], 0);
    cudaStreamWaitEvent(0, evInit, 0);   // tables/leg/mlp/dec1/castx ready

    for (int i = 0; i < NLAY; i++) {
        // side s2: P = w_inner[i] @ hAh (fp32), concurrent with spectral chain
        cudaStreamWaitEvent(s2, evL[i], 0);
        if (i == 0) cudaStreamWaitEvent(s2, evInit, 0);  // wInn ready
        k_hgemm<0, false, false, true, false><<<gE, 256, SMEMSZ, s2>>>(
            wInn + (long)i * E_ * E_, hAh, Pf, nullptr, nullptr, E_, HW, E_, E_, 0, 0, 0);
        cudaEventRecord(evP[i], s2);

        // main: spectral chain
        k_hgemm<1, false, false, false, false><<<gRF, 256, SMEMSZ>>>(
            hAh, Fh, nullptr, nullptr, nullptr, 46080, 184, W_, W_, 0, 0, 0);
        k_hgemm<2, false, false, false, false><<<gLF, 256, SMEMSZ>>>(
            legfH, xfh, nullptr, nullptr, nullptr, LM_, 512, H_, 184,
            (long)LM_ * 184, (long)H_ * 512, 0);
        cudaStreamWaitEvent(0, evA2[i], 0);
        k_hgemm<3, false, false, false, false><<<gSP, 256, SMEMSZ>>>(
            A2 + (long)i * LM_ * 512 * 512, cfh, nullptr, nullptr, nullptr, 512, 96, 512, 512,
            (long)512 * 512, (long)512 * 96, 0);
        k_hgemm<4, false, false, false, false><<<gLI, 256, SMEMSZ>>>(
            cf2h, legiH, nullptr, nullptr, nullptr, 512, 184, LM_, 96,
            (long)512 * 96, (long)LM_ * 184, 0);
        // irfft + inner skip fused: hBh = fp16( irfft(xf2h) + P )
        cudaStreamWaitEvent(0, evP[i], 0);
        k_hgemm<0, false, true, false, true><<<gIR, 256, SMEMSZ>>>(
            xf2h, Gih, nullptr, Pf, hBh, 46080, W_, 182, 184, 0, 0, 0);
        // t_h = fp16( gelu(w_mlp1 @ hBh) )
        k_hgemm<0, true, false, false, true><<<gH, 256, SMEMSZ>>>(
            wM1 + (long)i * HID_ * E_, hBh, hA, nullptr, tH, HID_, HW, E_, E_, 0, 0, 0);
        // hA = w_mlp2 @ t_h + hA ; refresh hAh
        k_hgemm<0, false, true, true, true><<<gE, 256, SMEMSZ>>>(
            wM2 + (long)i * E_ * HID_, tH, hA, hA, hAh, E_, HW, HID_, HID_, 0, 0, 0);
        if (i + 1 < NLAY) cudaEventRecord(evL[i + 1], 0);
    }

    k_hgemm<0, true, false, false, true><<<gE, 256, SMEMSZ>>>(wDec1, hAh, hA, nullptr,
                                                              tH, E_, HW, 258, 264, 0, 0, 0);
    k_dec2<<<(HW + 255) / 256, 256>>>(dec_w2, out);
}